// round 3
// baseline (speedup 1.0000x reference)
#include <cuda_runtime.h>
#include <math_constants.h>

// Problem constants (fixed shapes per reference):
//   h_P : [16384, 100] f32
//   h   : [16384]      f32
//   volP: [8192, 100]  f32
// Output f32 buffer of 32768 elems:
//   [0      : 8192 )  tot_ind_val
//   [8192   : 16384)  tot_ind (as float)
//   [16384  : 32768)  g = bincount(tot_ind)/8192

#define NUM_P   16384
#define DIM     100
#define KQ      25      // DIM / 4
#define BATN    8192
#define BM      128     // p-tile rows
#define BN      64      // n-tile columns
#define BNR     128     // replicated X row width (2x BN)
#define NTHREADS 256

// dynamic smem layout (floats):
//   XsR [DIM][BNR]  = 12800   (each x value duplicated: {x,x} pairs)
//   Ps  [DIM][BM]   = 12800
//   hs  [BM]        = 128
#define SMEM_FLOATS (DIM*BNR + DIM*BM + BM)

typedef unsigned long long u64;

__device__ __forceinline__ u64 ffma2(u64 a, u64 b, u64 c) {
    u64 d;
    asm("fma.rn.f32x2 %0, %1, %2, %3;" : "=l"(d) : "l"(a), "l"(b), "l"(c));
    return d;
}
__device__ __forceinline__ float f2_lo(u64 v) { return __uint_as_float((unsigned)v); }
__device__ __forceinline__ float f2_hi(u64 v) { return __uint_as_float((unsigned)(v >> 32)); }

__global__ void zero_g_kernel(float* __restrict__ g) {
    int i = blockIdx.x * blockDim.x + threadIdx.x;
    if (i < NUM_P) g[i] = 0.0f;
}

__global__ __launch_bounds__(NTHREADS, 1)
void ot_argmax_kernel(const float* __restrict__ P,
                      const float* __restrict__ h,
                      const float* __restrict__ X,
                      float* __restrict__ out) {
    extern __shared__ float smem[];
    float* XsR = smem;                  // [DIM][BNR] k-major, value-duplicated
    float* Ps  = smem + DIM * BNR;      // [DIM][BM]  k-major
    float* hs  = Ps + DIM * BM;         // [BM]

    const int tid = threadIdx.x;
    const int tx  = tid & 15;           // n-group: columns tx*4 .. tx*4+3
    const int ty  = tid >> 4;           // p-group: rows    ty*8 .. ty*8+7
    const int nbase = blockIdx.x * BN;

    // ---- Load X tile once, transposed + duplicated: XsR[k][2c]=XsR[k][2c+1]=x[c]
    for (int idx = tid; idx < KQ * BN; idx += NTHREADS) {
        int kq  = idx >> 6;             // 0..24
        int col = idx & 63;             // 0..63
        float4 v = reinterpret_cast<const float4*>(X)[(nbase + col) * KQ + kq];
        reinterpret_cast<float2*>(XsR + (4*kq + 0) * BNR)[col] = make_float2(v.x, v.x);
        reinterpret_cast<float2*>(XsR + (4*kq + 1) * BNR)[col] = make_float2(v.y, v.y);
        reinterpret_cast<float2*>(XsR + (4*kq + 2) * BNR)[col] = make_float2(v.z, v.z);
        reinterpret_cast<float2*>(XsR + (4*kq + 3) * BNR)[col] = make_float2(v.w, v.w);
    }

    float bestv[4];
    int   besti[4];
#pragma unroll
    for (int i = 0; i < 4; i++) { bestv[i] = -CUDART_INF_F; besti[i] = 0; }

    const float* xrow = XsR + tx * 8;   // replicated floats for cols tx*4..tx*4+3
    const float* prow = Ps  + ty * 8;

    for (int pt = 0; pt < NUM_P; pt += BM) {
        __syncthreads();   // protect Ps/hs from previous iteration's readers
        // ---- Load P tile transposed into Ps[k][p]
        for (int idx = tid; idx < KQ * BM; idx += NTHREADS) {
            int kq  = idx >> 7;         // 0..24
            int row = idx & 127;        // 0..127
            float4 v = reinterpret_cast<const float4*>(P)[(pt + row) * KQ + kq];
            Ps[(4*kq + 0) * BM + row] = v.x;
            Ps[(4*kq + 1) * BM + row] = v.y;
            Ps[(4*kq + 2) * BM + row] = v.z;
            Ps[(4*kq + 3) * BM + row] = v.w;
        }
        if (tid < BM) hs[tid] = h[pt + tid];
        __syncthreads();

        // ---- 128x64 score tile: acc[j2][i] packs p = ty*8+2*j2 (lo), +1 (hi)
        u64 acc[4][4];
#pragma unroll
        for (int j = 0; j < 4; j++)
#pragma unroll
            for (int i = 0; i < 4; i++) acc[j][i] = 0ull;

#pragma unroll 5
        for (int k = 0; k < DIM; k++) {
            ulonglong2 xa = *reinterpret_cast<const ulonglong2*>(xrow + k * BNR);
            ulonglong2 xb = *reinterpret_cast<const ulonglong2*>(xrow + k * BNR + 4);
            ulonglong2 pa = *reinterpret_cast<const ulonglong2*>(prow + k * BM);
            ulonglong2 pb = *reinterpret_cast<const ulonglong2*>(prow + k * BM + 4);
            u64 xr[4] = {xa.x, xa.y, xb.x, xb.y};   // {x_i, x_i}
            u64 pr[4] = {pa.x, pa.y, pb.x, pb.y};   // {p_{2j}, p_{2j+1}}
#pragma unroll
            for (int j = 0; j < 4; j++)
#pragma unroll
                for (int i = 0; i < 4; i++)
                    acc[j][i] = ffma2(pr[j], xr[i], acc[j][i]);
        }

        // ---- Fold into running (max, argmax). Ascending p (j2 asc, lo then hi)
        // with strict '>' keeps the first maximal index (jnp.argmax semantics).
#pragma unroll
        for (int j = 0; j < 4; j++) {
            int   pg = pt + ty * 8 + 2 * j;
            float h0 = hs[ty * 8 + 2 * j];
            float h1 = hs[ty * 8 + 2 * j + 1];
#pragma unroll
            for (int i = 0; i < 4; i++) {
                float s0 = f2_lo(acc[j][i]) + h0;
                float s1 = f2_hi(acc[j][i]) + h1;
                if (s0 > bestv[i]) { bestv[i] = s0; besti[i] = pg; }
                if (s1 > bestv[i]) { bestv[i] = s1; besti[i] = pg + 1; }
            }
        }
    }

    // ---- Cross-thread reduce over the 16 p-groups per column. Reuse Ps memory.
    __syncthreads();
    float* rv = Ps;                                      // [BN][16] floats
    int*   ri = reinterpret_cast<int*>(Ps + BN * 16);    // [BN][16] ints
#pragma unroll
    for (int i = 0; i < 4; i++) {
        int n = tx * 4 + i;
        rv[n * 16 + ty] = bestv[i];
        ri[n * 16 + ty] = besti[i];
    }
    __syncthreads();

    if (tid < BN) {
        int n = tid;
        float bv = rv[n * 16];
        int   bi = ri[n * 16];
#pragma unroll
        for (int t = 1; t < 16; t++) {
            float v  = rv[n * 16 + t];
            int   ix = ri[n * 16 + t];
            if (v > bv || (v == bv && ix < bi)) { bv = v; bi = ix; }
        }
        int ng = nbase + n;
        out[ng]        = bv;                 // tot_ind_val
        out[BATN + ng] = (float)bi;          // tot_ind (cast to f32)
        atomicAdd(&out[2 * BATN + bi], 1.0f / (float)BATN);   // g
    }
}

extern "C" void kernel_launch(void* const* d_in, const int* in_sizes, int n_in,
                              void* d_out, int out_size) {
    const float* P = (const float*)d_in[0];   // h_P [16384,100]
    const float* h = (const float*)d_in[1];   // h   [16384]
    const float* X = (const float*)d_in[2];   // volP[8192,100]
    float* out = (float*)d_out;

    (void)in_sizes; (void)n_in; (void)out_size;

    static bool attr_set = false;
    if (!attr_set) {
        cudaFuncSetAttribute(ot_argmax_kernel,
                             cudaFuncAttributeMaxDynamicSharedMemorySize,
                             SMEM_FLOATS * (int)sizeof(float));
        attr_set = true;
    }

    // Zero the g region (d_out is poisoned), then the fused GEMM+argmax.
    zero_g_kernel<<<(NUM_P + 255) / 256, 256>>>(out + 2 * BATN);
    ot_argmax_kernel<<<BATN / BN, NTHREADS, SMEM_FLOATS * sizeof(float)>>>(P, h, X, out);
}

// round 5
// speedup vs baseline: 1.7869x; 1.7869x over previous
#include <cuda_runtime.h>
#include <cuda_bf16.h>
#include <math_constants.h>
#include <cstdint>

// ============================================================================
// scores = h_P @ volP^T + h ; per-column (over p) max/argmax ; bincount/8192.
//   h_P [16384,100] f32 ; h [16384] f32 ; volP [8192,100] f32
//   out f32[32768] = [tot_ind_val(8192) | tot_ind(8192) | g(16384)]
//
// 3-way bf16 split (hi/mid/lo), 6 cross products folded into ONE bf16 GEMM by
// K-expansion:  A' (volP) K-blocks [ah ah am am ah al],
//               B' (h_P)  K-blocks [bh bm bh bm bl bh]   -> K = 6*112 = 672.
// fp32 accumulation via mma.sync.m16n8k16 (legacy HMMA; valid on compute_100).
// Error ~2^-27 * |a||b|*K ~ 2e-7  << min top-2 score gap (~5e-5).
// ============================================================================

#define NUM_P   16384
#define BATN    8192
#define DIM     100
#define KP      112
#define KEXP    672           // 6 * 112
#define KSTEPS  42            // 672 / 16
#define PCHUNKS 4
#define PCH     (NUM_P / PCHUNKS)   // 4096
#define PTILES  (PCH / 128)         // 32

// smem: 4 stages x (A 128x24bf16 + B 128x24bf16) = 4 x 12288 = 49152
// reduce buffers: rv 4*128 f32 (2048) + ri 4*128 i32 (2048)
#define STAGE_B     12288
#define B_OFF       6144
#define SMEM_RED    49152
#define SMEM_TOTAL  (49152 + 4096)

// ---------------- device scratch ----------------
__device__ __nv_bfloat16 g_A[(size_t)BATN * KEXP];    // 11 MB (volP expanded)
__device__ __nv_bfloat16 g_B[(size_t)NUM_P * KEXP];   // 22 MB (h_P expanded)
__device__ float g_pv[PCHUNKS * BATN];
__device__ int   g_pi[PCHUNKS * BATN];

// ---------------- asm helpers ----------------
__device__ __forceinline__ uint32_t smem_u32(const void* p) {
    uint32_t a;
    asm("{ .reg .u64 t; cvta.to.shared.u64 t, %1; cvt.u32.u64 %0, t; }" : "=r"(a) : "l"(p));
    return a;
}
__device__ __forceinline__ void cp16(uint32_t saddr, const void* gptr) {
    asm volatile("cp.async.cg.shared.global [%0], [%1], 16;"
                 :: "r"(saddr), "l"(__cvta_generic_to_global((void*)gptr)) : "memory");
}
#define CP_COMMIT() asm volatile("cp.async.commit_group;" ::: "memory")
#define CP_WAIT(n)  asm volatile("cp.async.wait_group %0;" :: "n"(n) : "memory")

#define LDSM4(r, addr) \
    asm volatile("ldmatrix.sync.aligned.m8n8.x4.shared.b16 {%0,%1,%2,%3}, [%4];" \
        : "=r"((r)[0]), "=r"((r)[1]), "=r"((r)[2]), "=r"((r)[3]) : "r"(addr))

#define MMA16816(c, a, b0, b1) \
    asm volatile("mma.sync.aligned.m16n8k16.row.col.f32.bf16.bf16.f32 " \
        "{%0,%1,%2,%3},{%4,%5,%6,%7},{%8,%9},{%0,%1,%2,%3};" \
        : "+f"((c)[0]), "+f"((c)[1]), "+f"((c)[2]), "+f"((c)[3]) \
        : "r"((a)[0]), "r"((a)[1]), "r"((a)[2]), "r"((a)[3]), "r"(b0), "r"(b1))

// ---------------- kernel: zero g ----------------
__global__ void zero_g_kernel(float* __restrict__ g) {
    int i = blockIdx.x * blockDim.x + threadIdx.x;
    if (i < NUM_P) g[i] = 0.0f;
}

// ---------------- kernel: split + K-expand ----------------
__global__ void expand_kernel(const float* __restrict__ src,
                              __nv_bfloat16* __restrict__ dst,
                              int rows, int isB) {
    int idx = blockIdx.x * blockDim.x + threadIdx.x;
    if (idx >= rows * KP) return;
    int row = idx / KP, k = idx - row * KP;
    float x = (k < DIM) ? src[row * DIM + k] : 0.0f;
    __nv_bfloat16 hi = __float2bfloat16(x);
    float r1 = x - __bfloat162float(hi);
    __nv_bfloat16 mid = __float2bfloat16(r1);
    float r2 = r1 - __bfloat162float(mid);
    __nv_bfloat16 lo = __float2bfloat16(r2);
    __nv_bfloat16 v[6];
    if (isB) { v[0]=hi; v[1]=mid; v[2]=hi; v[3]=mid; v[4]=lo; v[5]=hi; }
    else     { v[0]=hi; v[1]=hi;  v[2]=mid; v[3]=mid; v[4]=hi; v[5]=lo; }
    size_t rb = (size_t)row * KEXP + k;
#pragma unroll
    for (int j = 0; j < 6; j++) dst[rb + (size_t)j * KP] = v[j];
}

// ---------------- main fused GEMM + argmax ----------------
__global__ __launch_bounds__(256, 2)
void ot_mma_kernel(const float* __restrict__ h) {
    extern __shared__ char smem[];
    const uint32_t smb = smem_u32(smem);
    const int tid = threadIdx.x;
    const int L   = tid & 31;
    const int wid = tid >> 5;
    const int wm  = wid >> 2;          // 0..1 : n-dim 64-row half
    const int wp  = wid & 3;           // 0..3 : p-dim 32-col slice
    const int nt  = blockIdx.x >> 2;   // 0..63
    const int pc  = blockIdx.x & 3;    // 0..3
    const int nbase  = nt * 128;
    const int pchunk = pc * PCH;
    const int mrow = wm * 64, prow = wp * 32;

    // ldmatrix lane offsets (A: rows n, B: rows p; both 24 bf16 = 48B stride)
    const int mat = L >> 3, l8 = L & 7;
    const int arow = ((mat & 1) << 3) + l8, akh = (mat >> 1) << 3;
    const int brow = ((mat >> 1) << 3) + l8, bkh = (mat & 1) << 3;
    uint32_t aoff[4], boff[2];
#pragma unroll
    for (int mi = 0; mi < 4; mi++)
        aoff[mi] = (uint32_t)(((mrow + mi * 16 + arow) * 24 + akh) * 2);
#pragma unroll
    for (int g = 0; g < 2; g++)
        boff[g] = (uint32_t)(B_OFF + ((prow + g * 16 + brow) * 24 + bkh) * 2);

    // cp.async per-thread chunk (128 rows x 2 x 16B per operand per stage)
    const int cr = tid >> 1, cc = tid & 1;
    const uint32_t dA = (uint32_t)(cr * 48 + cc * 16);
    const uint32_t dB = (uint32_t)(B_OFF + cr * 48 + cc * 16);
    const __nv_bfloat16* srcA = g_A + (size_t)(nbase + cr) * KEXP + cc * 8;

    float bv[4][2];
    int   bi[4][2];
#pragma unroll
    for (int mi = 0; mi < 4; mi++)
#pragma unroll
        for (int hf = 0; hf < 2; hf++) { bv[mi][hf] = -CUDART_INF_F; bi[mi][hf] = 0; }

    for (int pt = 0; pt < PTILES; pt++) {
        const int p0 = pchunk + pt * 128;
        const __nv_bfloat16* srcB = g_B + (size_t)(p0 + cr) * KEXP + cc * 8;
        __syncthreads();                       // previous tile's stages drained
        // prologue: stages 0..2
#pragma unroll
        for (int s = 0; s < 3; s++) {
            cp16(smb + s * STAGE_B + dA, srcA + s * 16);
            cp16(smb + s * STAGE_B + dB, srcB + s * 16);
            CP_COMMIT();
        }

        float acc[4][4][4];
#pragma unroll
        for (int mi = 0; mi < 4; mi++)
#pragma unroll
            for (int ni = 0; ni < 4; ni++)
#pragma unroll
                for (int q = 0; q < 4; q++) acc[mi][ni][q] = 0.0f;

#pragma unroll 2
        for (int ks = 0; ks < KSTEPS; ks++) {
            CP_WAIT(2);
            __syncthreads();
            const int nk = ks + 3;
            if (nk < KSTEPS) {
                const uint32_t st = smb + (uint32_t)(nk & 3) * STAGE_B;
                cp16(st + dA, srcA + nk * 16);
                cp16(st + dB, srcB + nk * 16);
            }
            CP_COMMIT();

            const uint32_t sb = smb + (uint32_t)(ks & 3) * STAGE_B;
            uint32_t af[4][4], bf[2][4];
#pragma unroll
            for (int mi = 0; mi < 4; mi++) LDSM4(af[mi], sb + aoff[mi]);
#pragma unroll
            for (int g = 0; g < 2; g++)    LDSM4(bf[g], sb + boff[g]);
#pragma unroll
            for (int mi = 0; mi < 4; mi++)
#pragma unroll
                for (int ni = 0; ni < 4; ni++) {
                    const int g = ni >> 1, q = (ni & 1) * 2;
                    MMA16816(acc[mi][ni], af[mi], bf[g][q], bf[g][q + 1]);
                }
        }

        // fold tile into running best (p ascending: ni asc, then col pair asc)
#pragma unroll
        for (int ni = 0; ni < 4; ni++) {
            const int pA = p0 + prow + ni * 8 + (L & 3) * 2;
            const float h0 = __ldg(h + pA), h1 = __ldg(h + pA + 1);
#pragma unroll
            for (int mi = 0; mi < 4; mi++)
#pragma unroll
                for (int hf = 0; hf < 2; hf++) {
                    float s0 = acc[mi][ni][hf * 2 + 0] + h0;
                    float s1 = acc[mi][ni][hf * 2 + 1] + h1;
                    if (s0 > bv[mi][hf]) { bv[mi][hf] = s0; bi[mi][hf] = pA; }
                    if (s1 > bv[mi][hf]) { bv[mi][hf] = s1; bi[mi][hf] = pA + 1; }
                }
        }
    }

    // cross-lane reduce (lanes sharing a row differ only in L&3; their p sets
    // are disjoint; tie -> smaller p wins)
    __syncthreads();
    float* rv = reinterpret_cast<float*>(smem + SMEM_RED);
    int*   ri = reinterpret_cast<int*>(smem + SMEM_RED + 2048);
#pragma unroll
    for (int mi = 0; mi < 4; mi++)
#pragma unroll
        for (int hf = 0; hf < 2; hf++) {
            float v = bv[mi][hf];
            int   i = bi[mi][hf];
#pragma unroll
            for (int off = 1; off <= 2; off <<= 1) {
                float ov = __shfl_xor_sync(0xffffffffu, v, off);
                int   oi = __shfl_xor_sync(0xffffffffu, i, off);
                if (ov > v || (ov == v && oi < i)) { v = ov; i = oi; }
            }
            if ((L & 3) == 0) {
                int row = mrow + mi * 16 + (L >> 2) + hf * 8;
                rv[wp * 128 + row] = v;
                ri[wp * 128 + row] = i;
            }
        }
    __syncthreads();
    if (tid < 128) {
        float v = rv[tid]; int i = ri[tid];
#pragma unroll
        for (int w = 1; w < 4; w++) {
            float ov = rv[w * 128 + tid]; int oi = ri[w * 128 + tid];
            if (ov > v) { v = ov; i = oi; }   // wp ascending = p ascending
        }
        g_pv[pc * BATN + nbase + tid] = v;
        g_pi[pc * BATN + nbase + tid] = i;
    }
}

// ---------------- combine chunks + outputs + bincount ----------------
__global__ void combine_kernel(float* __restrict__ out) {
    int n = blockIdx.x * blockDim.x + threadIdx.x;
    if (n >= BATN) return;
    float v = g_pv[n]; int i = g_pi[n];
#pragma unroll
    for (int c = 1; c < PCHUNKS; c++) {
        float cv = g_pv[c * BATN + n]; int ci = g_pi[c * BATN + n];
        if (cv > v) { v = cv; i = ci; }       // chunks ascending in p
    }
    out[n]        = v;
    out[BATN + n] = (float)i;
    atomicAdd(&out[2 * BATN + i], 1.0f / (float)BATN);
}

// ---------------- launch ----------------
extern "C" void kernel_launch(void* const* d_in, const int* in_sizes, int n_in,
                              void* d_out, int out_size) {
    const float* P = (const float*)d_in[0];   // h_P [16384,100]
    const float* h = (const float*)d_in[1];   // h   [16384]
    const float* X = (const float*)d_in[2];   // volP[8192,100]
    float* out = (float*)d_out;
    (void)in_sizes; (void)n_in; (void)out_size;

    static bool attr_set = false;
    if (!attr_set) {
        cudaFuncSetAttribute(ot_mma_kernel,
                             cudaFuncAttributeMaxDynamicSharedMemorySize, SMEM_TOTAL);
        attr_set = true;
    }

    __nv_bfloat16* a; cudaGetSymbolAddress((void**)&a, g_A);
    __nv_bfloat16* b; cudaGetSymbolAddress((void**)&b, g_B);

    zero_g_kernel<<<(NUM_P + 255) / 256, 256>>>(out + 2 * BATN);
    expand_kernel<<<(BATN  * KP + 255) / 256, 256>>>(X, a, BATN,  0);
    expand_kernel<<<(NUM_P * KP + 255) / 256, 256>>>(P, b, NUM_P, 1);
    ot_mma_kernel<<<64 * PCHUNKS, 256, SMEM_TOTAL>>>(h);
    combine_kernel<<<(BATN + 255) / 256, 256>>>(out);
}

// round 6
// speedup vs baseline: 3.1789x; 1.7790x over previous
#include <cuda_runtime.h>
#include <cuda_fp16.h>
#include <math_constants.h>
#include <cstdint>

// ============================================================================
// scores = h_P @ volP^T + h ; per-column (over p) max/argmax ; bincount/8192.
//   h_P [16384,100] f32 ; h [16384] f32 ; volP [8192,100] f32
//   out f32[32768] = [tot_ind_val(8192) | tot_ind(8192) | g(16384)]
//
// 2-way fp16 split (hi/lo, 10+ mantissa bits each), 3 cross products folded
// into ONE fp16 GEMM by K-expansion:
//   A' (volP) K-blocks [ah ah al],  B' (h_P) K-blocks [bh bl bh]
//   -> K = 3*112 = 336.  Dropped ll term ~2^-22 -> score error ~1e-6.
// fp32 accumulation via mma.sync.m16n8k16.f32.f16.f16.f32 (sm_80+ PTX).
// ============================================================================

#define NUM_P   16384
#define BATN    8192
#define DIM     100
#define KP      112
#define KEXP    336           // 3 * 112
#define KSTEPS  21            // 336 / 16
#define PCHUNKS 8
#define PCH     (NUM_P / PCHUNKS)   // 2048
#define PTILES  (PCH / 128)         // 16

// smem: 4 stages x (A 128x24fp16 + B 128x24fp16) = 4 x 12288 = 49152
// reduce buffers: rv 4*128 f32 (2048) + ri 4*128 i32 (2048)
#define STAGE_B     12288
#define B_OFF       6144
#define SMEM_RED    49152
#define SMEM_TOTAL  (49152 + 4096)

// ---------------- device scratch ----------------
__device__ __half g_A[(size_t)BATN * KEXP];    // 5.5 MB (volP expanded)
__device__ __half g_B[(size_t)NUM_P * KEXP];   // 11 MB (h_P expanded)
__device__ float g_pv[PCHUNKS * BATN];
__device__ int   g_pi[PCHUNKS * BATN];

// ---------------- asm helpers ----------------
__device__ __forceinline__ uint32_t smem_u32(const void* p) {
    uint32_t a;
    asm("{ .reg .u64 t; cvta.to.shared.u64 t, %1; cvt.u32.u64 %0, t; }" : "=r"(a) : "l"(p));
    return a;
}
__device__ __forceinline__ void cp16(uint32_t saddr, const void* gptr) {
    asm volatile("cp.async.cg.shared.global [%0], [%1], 16;"
                 :: "r"(saddr), "l"(__cvta_generic_to_global((void*)gptr)) : "memory");
}
#define CP_COMMIT() asm volatile("cp.async.commit_group;" ::: "memory")
#define CP_WAIT(n)  asm volatile("cp.async.wait_group %0;" :: "n"(n) : "memory")

#define LDSM4(r, addr) \
    asm volatile("ldmatrix.sync.aligned.m8n8.x4.shared.b16 {%0,%1,%2,%3}, [%4];" \
        : "=r"((r)[0]), "=r"((r)[1]), "=r"((r)[2]), "=r"((r)[3]) : "r"(addr))

#define MMA16816(c, a, b0, b1) \
    asm volatile("mma.sync.aligned.m16n8k16.row.col.f32.f16.f16.f32 " \
        "{%0,%1,%2,%3},{%4,%5,%6,%7},{%8,%9},{%0,%1,%2,%3};" \
        : "+f"((c)[0]), "+f"((c)[1]), "+f"((c)[2]), "+f"((c)[3]) \
        : "r"((a)[0]), "r"((a)[1]), "r"((a)[2]), "r"((a)[3]), "r"(b0), "r"(b1))

// ---------------- kernel: zero g ----------------
__global__ void zero_g_kernel(float* __restrict__ g) {
    int i = blockIdx.x * blockDim.x + threadIdx.x;
    if (i < NUM_P) g[i] = 0.0f;
}

// ---------------- kernel: fp16 split + K-expand ----------------
__global__ void expand_kernel(const float* __restrict__ src,
                              __half* __restrict__ dst,
                              int rows, int isB) {
    int idx = blockIdx.x * blockDim.x + threadIdx.x;
    if (idx >= rows * KP) return;
    int row = idx / KP, k = idx - row * KP;
    float x = (k < DIM) ? src[row * DIM + k] : 0.0f;
    __half hi = __float2half_rn(x);
    __half lo = __float2half_rn(x - __half2float(hi));
    __half v[3];
    if (isB) { v[0] = hi; v[1] = lo; v[2] = hi; }   // [bh bl bh]
    else     { v[0] = hi; v[1] = hi; v[2] = lo; }   // [ah ah al]
    size_t rb = (size_t)row * KEXP + k;
#pragma unroll
    for (int j = 0; j < 3; j++) dst[rb + (size_t)j * KP] = v[j];
}

// ---------------- main fused GEMM + argmax ----------------
__global__ __launch_bounds__(256, 2)
void ot_mma_kernel(const float* __restrict__ h) {
    extern __shared__ char smem[];
    const uint32_t smb = smem_u32(smem);
    const int tid = threadIdx.x;
    const int L   = tid & 31;
    const int wid = tid >> 5;
    const int wm  = wid >> 2;          // 0..1 : n-dim 64-row half
    const int wp  = wid & 3;           // 0..3 : p-dim 32-col slice
    const int nt  = blockIdx.x >> 3;   // 0..63
    const int pc  = blockIdx.x & 7;    // 0..7
    const int nbase  = nt * 128;
    const int pchunk = pc * PCH;
    const int mrow = wm * 64, prow = wp * 32;

    // ldmatrix lane offsets (A: rows n, B: rows p; both 24 fp16 = 48B stride)
    const int mat = L >> 3, l8 = L & 7;
    const int arow = ((mat & 1) << 3) + l8, akh = (mat >> 1) << 3;
    const int brow = ((mat >> 1) << 3) + l8, bkh = (mat & 1) << 3;
    uint32_t aoff[4], boff[2];
#pragma unroll
    for (int mi = 0; mi < 4; mi++)
        aoff[mi] = (uint32_t)(((mrow + mi * 16 + arow) * 24 + akh) * 2);
#pragma unroll
    for (int g = 0; g < 2; g++)
        boff[g] = (uint32_t)(B_OFF + ((prow + g * 16 + brow) * 24 + bkh) * 2);

    // cp.async per-thread chunk (128 rows x 2 x 16B per operand per stage)
    const int cr = tid >> 1, cc = tid & 1;
    const uint32_t dA = (uint32_t)(cr * 48 + cc * 16);
    const uint32_t dB = (uint32_t)(B_OFF + cr * 48 + cc * 16);
    const __half* srcA = g_A + (size_t)(nbase + cr) * KEXP + cc * 8;

    float bv[4][2];
    int   bi[4][2];
#pragma unroll
    for (int mi = 0; mi < 4; mi++)
#pragma unroll
        for (int hf = 0; hf < 2; hf++) { bv[mi][hf] = -CUDART_INF_F; bi[mi][hf] = 0; }

    for (int pt = 0; pt < PTILES; pt++) {
        const int p0 = pchunk + pt * 128;
        const __half* srcB = g_B + (size_t)(p0 + cr) * KEXP + cc * 8;
        __syncthreads();                       // previous tile's stages drained
        // prologue: stages 0..2
#pragma unroll
        for (int s = 0; s < 3; s++) {
            cp16(smb + s * STAGE_B + dA, srcA + s * 16);
            cp16(smb + s * STAGE_B + dB, srcB + s * 16);
            CP_COMMIT();
        }

        float acc[4][4][4];
#pragma unroll
        for (int mi = 0; mi < 4; mi++)
#pragma unroll
            for (int ni = 0; ni < 4; ni++)
#pragma unroll
                for (int q = 0; q < 4; q++) acc[mi][ni][q] = 0.0f;

#pragma unroll 3
        for (int ks = 0; ks < KSTEPS; ks++) {
            CP_WAIT(2);
            __syncthreads();
            const int nk = ks + 3;
            if (nk < KSTEPS) {
                const uint32_t st = smb + (uint32_t)(nk & 3) * STAGE_B;
                cp16(st + dA, srcA + nk * 16);
                cp16(st + dB, srcB + nk * 16);
            }
            CP_COMMIT();

            const uint32_t sb = smb + (uint32_t)(ks & 3) * STAGE_B;
            uint32_t af[4][4], bf[2][4];
#pragma unroll
            for (int mi = 0; mi < 4; mi++) LDSM4(af[mi], sb + aoff[mi]);
#pragma unroll
            for (int g = 0; g < 2; g++)    LDSM4(bf[g], sb + boff[g]);
#pragma unroll
            for (int mi = 0; mi < 4; mi++)
#pragma unroll
                for (int ni = 0; ni < 4; ni++) {
                    const int g = ni >> 1, q = (ni & 1) * 2;
                    MMA16816(acc[mi][ni], af[mi], bf[g][q], bf[g][q + 1]);
                }
        }

        // fold tile into running best (p ascending: ni asc, then col pair asc)
#pragma unroll
        for (int ni = 0; ni < 4; ni++) {
            const int pA = p0 + prow + ni * 8 + (L & 3) * 2;
            const float h0 = __ldg(h + pA), h1 = __ldg(h + pA + 1);
#pragma unroll
            for (int mi = 0; mi < 4; mi++)
#pragma unroll
                for (int hf = 0; hf < 2; hf++) {
                    float s0 = acc[mi][ni][hf * 2 + 0] + h0;
                    float s1 = acc[mi][ni][hf * 2 + 1] + h1;
                    if (s0 > bv[mi][hf]) { bv[mi][hf] = s0; bi[mi][hf] = pA; }
                    if (s1 > bv[mi][hf]) { bv[mi][hf] = s1; bi[mi][hf] = pA + 1; }
                }
        }
    }

    // cross-lane reduce (lanes sharing a row differ only in L&3; their p sets
    // are disjoint; tie -> smaller p wins)
    __syncthreads();
    float* rv = reinterpret_cast<float*>(smem + SMEM_RED);
    int*   ri = reinterpret_cast<int*>(smem + SMEM_RED + 2048);
#pragma unroll
    for (int mi = 0; mi < 4; mi++)
#pragma unroll
        for (int hf = 0; hf < 2; hf++) {
            float v = bv[mi][hf];
            int   i = bi[mi][hf];
#pragma unroll
            for (int off = 1; off <= 2; off <<= 1) {
                float ov = __shfl_xor_sync(0xffffffffu, v, off);
                int   oi = __shfl_xor_sync(0xffffffffu, i, off);
                if (ov > v || (ov == v && oi < i)) { v = ov; i = oi; }
            }
            if ((L & 3) == 0) {
                int row = mrow + mi * 16 + (L >> 2) + hf * 8;
                rv[wp * 128 + row] = v;
                ri[wp * 128 + row] = i;
            }
        }
    __syncthreads();
    if (tid < 128) {
        float v = rv[tid]; int i = ri[tid];
#pragma unroll
        for (int w = 1; w < 4; w++) {
            float ov = rv[w * 128 + tid]; int oi = ri[w * 128 + tid];
            if (ov > v) { v = ov; i = oi; }   // wp ascending = p ascending
        }
        g_pv[pc * BATN + nbase + tid] = v;
        g_pi[pc * BATN + nbase + tid] = i;
    }
}

// ---------------- combine chunks + outputs + bincount ----------------
__global__ void combine_kernel(float* __restrict__ out) {
    int n = blockIdx.x * blockDim.x + threadIdx.x;
    if (n >= BATN) return;
    float v = g_pv[n]; int i = g_pi[n];
#pragma unroll
    for (int c = 1; c < PCHUNKS; c++) {
        float cv = g_pv[c * BATN + n]; int ci = g_pi[c * BATN + n];
        if (cv > v) { v = cv; i = ci; }       // chunks ascending in p
    }
    out[n]        = v;
    out[BATN + n] = (float)i;
    atomicAdd(&out[2 * BATN + i], 1.0f / (float)BATN);
}

// ---------------- launch ----------------
extern "C" void kernel_launch(void* const* d_in, const int* in_sizes, int n_in,
                              void* d_out, int out_size) {
    const float* P = (const float*)d_in[0];   // h_P [16384,100]
    const float* h = (const float*)d_in[1];   // h   [16384]
    const float* X = (const float*)d_in[2];   // volP[8192,100]
    float* out = (float*)d_out;
    (void)in_sizes; (void)n_in; (void)out_size;

    static bool attr_set = false;
    if (!attr_set) {
        cudaFuncSetAttribute(ot_mma_kernel,
                             cudaFuncAttributeMaxDynamicSharedMemorySize, SMEM_TOTAL);
        attr_set = true;
    }

    __half* a; cudaGetSymbolAddress((void**)&a, g_A);
    __half* b; cudaGetSymbolAddress((void**)&b, g_B);

    zero_g_kernel<<<(NUM_P + 255) / 256, 256>>>(out + 2 * BATN);
    expand_kernel<<<(BATN  * KP + 255) / 256, 256>>>(X, a, BATN,  0);
    expand_kernel<<<(NUM_P * KP + 255) / 256, 256>>>(P, b, NUM_P, 1);
    ot_mma_kernel<<<64 * PCHUNKS, 256, SMEM_TOTAL>>>(h);
    combine_kernel<<<(BATN + 255) / 256, 256>>>(out);
}

// round 7
// speedup vs baseline: 3.7124x; 1.1678x over previous
#include <cuda_runtime.h>
#include <cuda_fp16.h>
#include <math_constants.h>
#include <cstdint>

// ============================================================================
// scores = h_P @ volP^T + h ; per-column (over p) max/argmax ; bincount/8192.
//   h_P [16384,100] f32 ; h [16384] f32 ; volP [8192,100] f32
//   out f32[32768] = [tot_ind_val(8192) | tot_ind(8192) | g(16384)]
//
// 2-way fp16 split, 3 cross products in ONE fp16 GEMM via K-concatenation:
//   A' (volP): [ah(100) | ah(100) | al(100) | 0(20)]   K = 320
//   B' (h_P) : [bh(100) | bl(100) | bh(100) | 0(20)]
// fp32 accumulate via mma.sync.m16n8k16 (sm_80+ PTX, valid on compute_100).
// 32-K stages, 3-stage cp.async pipeline, flattened across p-tiles (no drains).
// ============================================================================

#define NUM_P   16384
#define BATN    8192
#define DIM     100
#define KEXP    320
#define KSTEPS  10            // 32-K steps per p-tile
#define PCHUNKS 8
#define PCH     (NUM_P / PCHUNKS)   // 2048
#define PTILES  (PCH / 128)         // 16
#define TOT     (PTILES * KSTEPS)   // 160

// stage: A 128 rows x 40 half (80B) + B same -> 20480B ; 3 stages
#define ROW_B       80
#define B_OFF       10240
#define STAGE_B     20480
#define SMEM_RED    61440
#define SMEM_TOTAL  (61440 + 4096)

// ---------------- device scratch ----------------
__device__ __half g_A[(size_t)BATN  * KEXP];   // 5.2 MB
__device__ __half g_B[(size_t)NUM_P * KEXP];   // 10.5 MB
__device__ float g_pv[PCHUNKS * BATN];
__device__ int   g_pi[PCHUNKS * BATN];

// ---------------- asm helpers ----------------
__device__ __forceinline__ uint32_t smem_u32(const void* p) {
    uint32_t a;
    asm("{ .reg .u64 t; cvta.to.shared.u64 t, %1; cvt.u32.u64 %0, t; }" : "=r"(a) : "l"(p));
    return a;
}
__device__ __forceinline__ void cp16(uint32_t saddr, const void* gptr) {
    asm volatile("cp.async.cg.shared.global [%0], [%1], 16;"
                 :: "r"(saddr), "l"(__cvta_generic_to_global((void*)gptr)) : "memory");
}
#define CP_COMMIT() asm volatile("cp.async.commit_group;" ::: "memory")
#define CP_WAIT(n)  asm volatile("cp.async.wait_group %0;" :: "n"(n) : "memory")

#define LDSM4(r, addr) \
    asm volatile("ldmatrix.sync.aligned.m8n8.x4.shared.b16 {%0,%1,%2,%3}, [%4];" \
        : "=r"((r)[0]), "=r"((r)[1]), "=r"((r)[2]), "=r"((r)[3]) : "r"(addr))

#define MMA16816(c, a, b0, b1) \
    asm volatile("mma.sync.aligned.m16n8k16.row.col.f32.f16.f16.f32 " \
        "{%0,%1,%2,%3},{%4,%5,%6,%7},{%8,%9},{%0,%1,%2,%3};" \
        : "+f"((c)[0]), "+f"((c)[1]), "+f"((c)[2]), "+f"((c)[3]) \
        : "r"((a)[0]), "r"((a)[1]), "r"((a)[2]), "r"((a)[3]), "r"(b0), "r"(b1))

// ---------------- kernel: zero g ----------------
__global__ void zero_g_kernel(float* __restrict__ g) {
    int i = blockIdx.x * blockDim.x + threadIdx.x;
    if (i < NUM_P) g[i] = 0.0f;
}

// ---------------- kernel: fp16 split + K-concat expand ----------------
__global__ void expand_kernel(const float* __restrict__ src,
                              __half* __restrict__ dst,
                              int rows, int isB) {
    int idx = blockIdx.x * blockDim.x + threadIdx.x;
    if (idx >= rows * KEXP) return;
    int row = idx / KEXP, k = idx - row * KEXP;
    int blk = (k < 100) ? 0 : (k < 200) ? 1 : (k < 300) ? 2 : 3;
    int kk = k - blk * 100;
    __half o = __float2half_rn(0.0f);
    if (blk < 3) {
        float x = src[row * DIM + kk];
        __half hi = __float2half_rn(x);
        if (isB) {      // [bh bl bh]
            if (blk == 1) o = __float2half_rn(x - __half2float(hi));
            else          o = hi;
        } else {        // [ah ah al]
            if (blk == 2) o = __float2half_rn(x - __half2float(hi));
            else          o = hi;
        }
    }
    dst[idx] = o;
}

// ---------------- main fused GEMM + argmax ----------------
__global__ __launch_bounds__(256, 2)
void ot_mma_kernel(const float* __restrict__ h) {
    extern __shared__ char smem[];
    const uint32_t smb = smem_u32(smem);
    const int tid = threadIdx.x;
    const int L   = tid & 31;
    const int wid = tid >> 5;
    const int wm  = wid >> 2;          // 0..1 : n-dim half
    const int wp  = wid & 3;           // 0..3 : p-dim slice
    const int nt  = blockIdx.x >> 3;
    const int pc  = blockIdx.x & 7;
    const int nbase  = nt * 128;
    const int pchunk = pc * PCH;
    const int mrow = wm * 64, prow = wp * 32;

    // ldmatrix lane offsets (row stride 40 half = 80B; conflict-free)
    const int mat = L >> 3, l8 = L & 7;
    const int arow = ((mat & 1) << 3) + l8, akh = (mat >> 1) << 3;
    const int brow = ((mat >> 1) << 3) + l8, bkh = (mat & 1) << 3;
    uint32_t aoff[4], boff[2];
#pragma unroll
    for (int mi = 0; mi < 4; mi++)
        aoff[mi] = (uint32_t)(((mrow + mi * 16 + arow) * 40 + akh) * 2);
#pragma unroll
    for (int g = 0; g < 2; g++)
        boff[g] = (uint32_t)(B_OFF + ((prow + g * 16 + brow) * 40 + bkh) * 2);

    // cp.async mapping: thread -> rows {cr4, cr4+64}, 16B chunk cc4, per operand
    const int cr4 = tid >> 2, cc4 = tid & 3;
    const uint32_t dA = (uint32_t)(cr4 * ROW_B + cc4 * 16);
    const uint32_t dB = (uint32_t)(B_OFF + cr4 * ROW_B + cc4 * 16);
    const __half* bA = g_A + (size_t)(nbase  + cr4) * KEXP + cc4 * 8;
    const __half* bB = g_B + (size_t)(pchunk + cr4) * KEXP + cc4 * 8;

    // prologue: stages for steps 0,1 (tile 0, ks 0,1)
#pragma unroll
    for (int s = 0; s < 2; s++) {
        const uint32_t st = smb + (uint32_t)s * STAGE_B;
        cp16(st + dA,        bA + s * 32);
        cp16(st + dA + 5120, bA + (size_t)64 * KEXP + s * 32);
        cp16(st + dB,        bB + s * 32);
        cp16(st + dB + 5120, bB + (size_t)64 * KEXP + s * 32);
        CP_COMMIT();
    }

    float acc[4][4][4];
#pragma unroll
    for (int mi = 0; mi < 4; mi++)
#pragma unroll
        for (int ni = 0; ni < 4; ni++)
#pragma unroll
            for (int q = 0; q < 4; q++) acc[mi][ni][q] = 0.0f;

    float bv[4][2];
    int   bi[4][2];
#pragma unroll
    for (int mi = 0; mi < 4; mi++)
#pragma unroll
        for (int hf = 0; hf < 2; hf++) { bv[mi][hf] = -CUDART_INF_F; bi[mi][hf] = 0; }

    int ks = 0, p0 = pchunk;           // current tile state
    int pfk = 2;                       // prefetch k-step within its tile
    const __half* pB = bB;             // prefetch-tile B base

    for (int gs = 0; gs < TOT; gs++) {
        CP_WAIT(1);
        __syncthreads();

        // prefetch stage for step gs+2 (rolls across tile boundaries)
        if (gs + 2 < TOT) {
            const uint32_t st = smb + (uint32_t)((gs + 2) % 3) * STAGE_B;
            cp16(st + dA,        bA + pfk * 32);
            cp16(st + dA + 5120, bA + (size_t)64 * KEXP + pfk * 32);
            cp16(st + dB,        pB + pfk * 32);
            cp16(st + dB + 5120, pB + (size_t)64 * KEXP + pfk * 32);
        }
        CP_COMMIT();
        if (++pfk == KSTEPS) { pfk = 0; pB += (size_t)128 * KEXP; }

        // compute on stage gs: two 16-K halves
        const uint32_t sb = smb + (uint32_t)(gs % 3) * STAGE_B;
#pragma unroll
        for (int kh = 0; kh < 2; kh++) {
            const uint32_t ko = (uint32_t)kh * 32;
            uint32_t af[4][4], bf[2][4];
#pragma unroll
            for (int mi = 0; mi < 4; mi++) LDSM4(af[mi], sb + aoff[mi] + ko);
#pragma unroll
            for (int g = 0; g < 2; g++)    LDSM4(bf[g], sb + boff[g] + ko);
#pragma unroll
            for (int mi = 0; mi < 4; mi++)
#pragma unroll
                for (int ni = 0; ni < 4; ni++) {
                    const int g = ni >> 1, q = (ni & 1) * 2;
                    MMA16816(acc[mi][ni], af[mi], bf[g][q], bf[g][q + 1]);
                }
        }

        // end of p-tile: fold accumulators (register-only; no barrier needed)
        if (ks == KSTEPS - 1) {
#pragma unroll
            for (int ni = 0; ni < 4; ni++) {
                const int pA = p0 + prow + ni * 8 + (L & 3) * 2;
                const float h0 = __ldg(h + pA), h1 = __ldg(h + pA + 1);
#pragma unroll
                for (int mi = 0; mi < 4; mi++)
#pragma unroll
                    for (int hf = 0; hf < 2; hf++) {
                        float s0 = acc[mi][ni][hf * 2 + 0] + h0;
                        float s1 = acc[mi][ni][hf * 2 + 1] + h1;
                        if (s0 > bv[mi][hf]) { bv[mi][hf] = s0; bi[mi][hf] = pA; }
                        if (s1 > bv[mi][hf]) { bv[mi][hf] = s1; bi[mi][hf] = pA + 1; }
                        acc[mi][ni][hf * 2 + 0] = 0.0f;
                        acc[mi][ni][hf * 2 + 1] = 0.0f;
                    }
            }
            ks = 0; p0 += 128;
        } else {
            ks++;
        }
    }

    // cross-lane reduce (lanes sharing a row differ only in L&3; disjoint p sets)
    __syncthreads();
    float* rv = reinterpret_cast<float*>(smem + SMEM_RED);
    int*   ri = reinterpret_cast<int*>(smem + SMEM_RED + 2048);
#pragma unroll
    for (int mi = 0; mi < 4; mi++)
#pragma unroll
        for (int hf = 0; hf < 2; hf++) {
            float v = bv[mi][hf];
            int   i = bi[mi][hf];
#pragma unroll
            for (int off = 1; off <= 2; off <<= 1) {
                float ov = __shfl_xor_sync(0xffffffffu, v, off);
                int   oi = __shfl_xor_sync(0xffffffffu, i, off);
                if (ov > v || (ov == v && oi < i)) { v = ov; i = oi; }
            }
            if ((L & 3) == 0) {
                int row = mrow + mi * 16 + (L >> 2) + hf * 8;
                rv[wp * 128 + row] = v;
                ri[wp * 128 + row] = i;
            }
        }
    __syncthreads();
    if (tid < 128) {
        float v = rv[tid]; int i = ri[tid];
#pragma unroll
        for (int w = 1; w < 4; w++) {
            float ov = rv[w * 128 + tid]; int oi = ri[w * 128 + tid];
            if (ov > v) { v = ov; i = oi; }   // wp ascending = p ascending
        }
        g_pv[pc * BATN + nbase + tid] = v;
        g_pi[pc * BATN + nbase + tid] = i;
    }
}

// ---------------- combine chunks + outputs + bincount ----------------
__global__ void combine_kernel(float* __restrict__ out) {
    int n = blockIdx.x * blockDim.x + threadIdx.x;
    if (n >= BATN) return;
    float v = g_pv[n]; int i = g_pi[n];
#pragma unroll
    for (int c = 1; c < PCHUNKS; c++) {
        float cv = g_pv[c * BATN + n]; int ci = g_pi[c * BATN + n];
        if (cv > v) { v = cv; i = ci; }       // chunks ascending in p
    }
    out[n]        = v;
    out[BATN + n] = (float)i;
    atomicAdd(&out[2 * BATN + i], 1.0f / (float)BATN);
}

// ---------------- launch ----------------
extern "C" void kernel_launch(void* const* d_in, const int* in_sizes, int n_in,
                              void* d_out, int out_size) {
    const float* P = (const float*)d_in[0];   // h_P [16384,100]
    const float* h = (const float*)d_in[1];   // h   [16384]
    const float* X = (const float*)d_in[2];   // volP[8192,100]
    float* out = (float*)d_out;
    (void)in_sizes; (void)n_in; (void)out_size;

    static bool attr_set = false;
    if (!attr_set) {
        cudaFuncSetAttribute(ot_mma_kernel,
                             cudaFuncAttributeMaxDynamicSharedMemorySize, SMEM_TOTAL);
        attr_set = true;
    }

    __half* a; cudaGetSymbolAddress((void**)&a, g_A);
    __half* b; cudaGetSymbolAddress((void**)&b, g_B);

    zero_g_kernel<<<(NUM_P + 255) / 256, 256>>>(out + 2 * BATN);
    expand_kernel<<<((int)(BATN  * KEXP) + 255) / 256, 256>>>(X, a, BATN,  0);
    expand_kernel<<<((int)(NUM_P * KEXP) + 255) / 256, 256>>>(P, b, NUM_P, 1);
    ot_mma_kernel<<<64 * PCHUNKS, 256, SMEM_TOTAL>>>(h);
    combine_kernel<<<(BATN + 255) / 256, 256>>>(out);
}

// round 8
// speedup vs baseline: 4.0562x; 1.0926x over previous
#include <cuda_runtime.h>
#include <cuda_fp16.h>
#include <math_constants.h>
#include <cstdint>

// ============================================================================
// scores = h_P @ volP^T + h ; per-column (over p) max/argmax ; bincount/8192.
//   h_P [16384,100] f32 ; h [16384] f32 ; volP [8192,100] f32
//   out f32[32768] = [tot_ind_val(8192) | tot_ind(8192) | g(16384)]
//
// 2-way fp16 split, 3 cross products in ONE fp16 GEMM via K-concatenation:
//   A' (volP): [ah(100) | ah(100) | al(100) | 0(20)]   K = 320
//   B' (h_P) : [bh(100) | bl(100) | bh(100) | 0(20)]
// mma.sync.m16n8k16 fp32-accum. 128-thread CTAs (4 warps, tile 128n x 64p),
// occupancy 4 CTA/SM -> 4 independent pipelines per SMSP to hide barriers.
// ============================================================================

#define NUM_P   16384
#define BATN    8192
#define DIM     100
#define KEXP    320
#define KSTEPS  10                  // 32-K steps per p-tile
#define PCHUNKS 16
#define PCH     (NUM_P / PCHUNKS)   // 1024
#define PTILES  (PCH / 64)          // 16 (p-tile = 64)
#define TOT     (PTILES * KSTEPS)   // 160
#define THREADS 128

// stage: A 128 rows x 80B + B 64 rows x 80B = 15360B ; 3 stages
#define ROW_B       80
#define B_OFF       10240
#define STAGE_B     15360
#define SMEM_RED    46080           // 3*STAGE_B
#define SMEM_TOTAL  (46080 + 2048)

// ---------------- device scratch ----------------
__device__ __half g_A[(size_t)BATN  * KEXP];   // 5.2 MB
__device__ __half g_B[(size_t)NUM_P * KEXP];   // 10.5 MB
__device__ float g_pv[PCHUNKS * BATN];
__device__ int   g_pi[PCHUNKS * BATN];

// ---------------- asm helpers ----------------
__device__ __forceinline__ uint32_t smem_u32(const void* p) {
    uint32_t a;
    asm("{ .reg .u64 t; cvta.to.shared.u64 t, %1; cvt.u32.u64 %0, t; }" : "=r"(a) : "l"(p));
    return a;
}
__device__ __forceinline__ void cp16(uint32_t saddr, const void* gptr) {
    asm volatile("cp.async.cg.shared.global [%0], [%1], 16;"
                 :: "r"(saddr), "l"(__cvta_generic_to_global((void*)gptr)) : "memory");
}
#define CP_COMMIT() asm volatile("cp.async.commit_group;" ::: "memory")
#define CP_WAIT(n)  asm volatile("cp.async.wait_group %0;" :: "n"(n) : "memory")

#define LDSM4(r, addr) \
    asm volatile("ldmatrix.sync.aligned.m8n8.x4.shared.b16 {%0,%1,%2,%3}, [%4];" \
        : "=r"((r)[0]), "=r"((r)[1]), "=r"((r)[2]), "=r"((r)[3]) : "r"(addr))

#define MMA16816(c, a, b0, b1) \
    asm volatile("mma.sync.aligned.m16n8k16.row.col.f32.f16.f16.f32 " \
        "{%0,%1,%2,%3},{%4,%5,%6,%7},{%8,%9},{%0,%1,%2,%3};" \
        : "+f"((c)[0]), "+f"((c)[1]), "+f"((c)[2]), "+f"((c)[3]) \
        : "r"((a)[0]), "r"((a)[1]), "r"((a)[2]), "r"((a)[3]), "r"(b0), "r"(b1))

// ---------------- kernel: zero g ----------------
__global__ void zero_g_kernel(float* __restrict__ g) {
    int i = blockIdx.x * blockDim.x + threadIdx.x;
    if (i < NUM_P) g[i] = 0.0f;
}

// ---------------- kernel: fp16 split + K-concat expand ----------------
__global__ void expand_kernel(const float* __restrict__ src,
                              __half* __restrict__ dst,
                              int rows, int isB) {
    int idx = blockIdx.x * blockDim.x + threadIdx.x;
    if (idx >= rows * KEXP) return;
    int row = idx / KEXP, k = idx - row * KEXP;
    int blk = (k < 100) ? 0 : (k < 200) ? 1 : (k < 300) ? 2 : 3;
    int kk = k - blk * 100;
    __half o = __float2half_rn(0.0f);
    if (blk < 3) {
        float x = src[row * DIM + kk];
        __half hi = __float2half_rn(x);
        if (isB) {      // [bh bl bh]
            if (blk == 1) o = __float2half_rn(x - __half2float(hi));
            else          o = hi;
        } else {        // [ah ah al]
            if (blk == 2) o = __float2half_rn(x - __half2float(hi));
            else          o = hi;
        }
    }
    dst[idx] = o;
}

// ---------------- main fused GEMM + argmax ----------------
__global__ __launch_bounds__(THREADS, 4)
void ot_mma_kernel(const float* __restrict__ h) {
    extern __shared__ char smem[];
    const uint32_t smb = smem_u32(smem);
    const int tid = threadIdx.x;
    const int L   = tid & 31;
    const int wid = tid >> 5;          // 0..3
    const int wm  = wid >> 1;          // 0..1 : n-dim half (64 rows)
    const int wp  = wid & 1;           // 0..1 : p-dim slice (32 cols)
    const int nt  = blockIdx.x >> 4;   // 0..63
    const int pc  = blockIdx.x & 15;   // 0..15
    const int nbase  = nt * 128;
    const int pchunk = pc * PCH;
    const int mrow = wm * 64, prow = wp * 32;

    // ldmatrix lane offsets (row stride 80B; conflict-free mod 128B)
    const int mat = L >> 3, l8 = L & 7;
    const int arow = ((mat & 1) << 3) + l8, akh = (mat >> 1) << 3;
    const int brow = ((mat >> 1) << 3) + l8, bkh = (mat & 1) << 3;
    uint32_t aoff[4], boff[2];
#pragma unroll
    for (int mi = 0; mi < 4; mi++)
        aoff[mi] = (uint32_t)(((mrow + mi * 16 + arow) * 40 + akh) * 2);
#pragma unroll
    for (int g = 0; g < 2; g++)
        boff[g] = (uint32_t)(B_OFF + ((prow + g * 16 + brow) * 40 + bkh) * 2);

    // cp.async mapping: r = tid>>2 (0..31), cc = tid&3 (16B chunk), 6 passes
    //   passes 0..3 -> A rows r,r+32,r+64,r+96 ; passes 4,5 -> B rows r,r+32
    const int cr = tid >> 2, cc = tid & 3;
    const uint32_t dAc = (uint32_t)(cr * ROW_B + cc * 16);
    const uint32_t dBc = (uint32_t)(B_OFF + cr * ROW_B + cc * 16);
    const __half* bA = g_A + (size_t)(nbase  + cr) * KEXP + cc * 8;
    const __half* bB = g_B + (size_t)(pchunk + cr) * KEXP + cc * 8;

#define LOAD_STAGE(stageaddr, ksA, srcB_, ksB) do {                              \
    const uint32_t _st = (stageaddr);                                            \
    _Pragma("unroll")                                                            \
    for (int _i = 0; _i < 4; _i++)                                               \
        cp16(_st + dAc + (uint32_t)_i * 32 * ROW_B,                              \
             bA + (size_t)_i * 32 * KEXP + (ksA) * 32);                          \
    _Pragma("unroll")                                                            \
    for (int _i = 0; _i < 2; _i++)                                               \
        cp16(_st + dBc + (uint32_t)_i * 32 * ROW_B,                              \
             (srcB_) + (size_t)_i * 32 * KEXP + (ksB) * 32);                     \
} while (0)

    // prologue: stages for steps 0,1
#pragma unroll
    for (int s = 0; s < 2; s++) {
        LOAD_STAGE(smb + (uint32_t)s * STAGE_B, s, bB, s);
        CP_COMMIT();
    }

    float acc[4][4][4];
#pragma unroll
    for (int mi = 0; mi < 4; mi++)
#pragma unroll
        for (int ni = 0; ni < 4; ni++)
#pragma unroll
            for (int q = 0; q < 4; q++) acc[mi][ni][q] = 0.0f;

    float bv[4][2];
    int   bi[4][2];
#pragma unroll
    for (int mi = 0; mi < 4; mi++)
#pragma unroll
        for (int hf = 0; hf < 2; hf++) { bv[mi][hf] = -CUDART_INF_F; bi[mi][hf] = 0; }

    int ks = 0, p0 = pchunk;           // current tile state
    int pfk = 2;                       // prefetch k-step within its tile
    const __half* pB = bB;             // prefetch-tile B base

    for (int gs = 0; gs < TOT; gs++) {
        CP_WAIT(1);
        __syncthreads();

        // prefetch stage for step gs+2 (rolls across tile boundaries)
        if (gs + 2 < TOT) {
            LOAD_STAGE(smb + (uint32_t)((gs + 2) % 3) * STAGE_B, pfk, pB, pfk);
        }
        CP_COMMIT();
        if (++pfk == KSTEPS) { pfk = 0; pB += (size_t)64 * KEXP; }

        // compute on stage gs: two 16-K halves
        const uint32_t sb = smb + (uint32_t)(gs % 3) * STAGE_B;
#pragma unroll
        for (int kh = 0; kh < 2; kh++) {
            const uint32_t ko = (uint32_t)kh * 32;
            uint32_t af[4][4], bf[2][4];
#pragma unroll
            for (int mi = 0; mi < 4; mi++) LDSM4(af[mi], sb + aoff[mi] + ko);
#pragma unroll
            for (int g = 0; g < 2; g++)    LDSM4(bf[g], sb + boff[g] + ko);
#pragma unroll
            for (int mi = 0; mi < 4; mi++)
#pragma unroll
                for (int ni = 0; ni < 4; ni++) {
                    const int g = ni >> 1, q = (ni & 1) * 2;
                    MMA16816(acc[mi][ni], af[mi], bf[g][q], bf[g][q + 1]);
                }
        }

        // end of p-tile: fold accumulators (register-only; no barrier needed)
        if (ks == KSTEPS - 1) {
#pragma unroll
            for (int ni = 0; ni < 4; ni++) {
                const int pA = p0 + prow + ni * 8 + (L & 3) * 2;
                const float h0 = __ldg(h + pA), h1 = __ldg(h + pA + 1);
#pragma unroll
                for (int mi = 0; mi < 4; mi++)
#pragma unroll
                    for (int hf = 0; hf < 2; hf++) {
                        float s0 = acc[mi][ni][hf * 2 + 0] + h0;
                        float s1 = acc[mi][ni][hf * 2 + 1] + h1;
                        if (s0 > bv[mi][hf]) { bv[mi][hf] = s0; bi[mi][hf] = pA; }
                        if (s1 > bv[mi][hf]) { bv[mi][hf] = s1; bi[mi][hf] = pA + 1; }
                        acc[mi][ni][hf * 2 + 0] = 0.0f;
                        acc[mi][ni][hf * 2 + 1] = 0.0f;
                    }
            }
            ks = 0; p0 += 64;
        } else {
            ks++;
        }
    }

    // cross-lane reduce (lanes sharing a row differ only in L&3; disjoint p sets)
    __syncthreads();
    float* rv = reinterpret_cast<float*>(smem + SMEM_RED);
    int*   ri = reinterpret_cast<int*>(smem + SMEM_RED + 1024);
#pragma unroll
    for (int mi = 0; mi < 4; mi++)
#pragma unroll
        for (int hf = 0; hf < 2; hf++) {
            float v = bv[mi][hf];
            int   i = bi[mi][hf];
#pragma unroll
            for (int off = 1; off <= 2; off <<= 1) {
                float ov = __shfl_xor_sync(0xffffffffu, v, off);
                int   oi = __shfl_xor_sync(0xffffffffu, i, off);
                if (ov > v || (ov == v && oi < i)) { v = ov; i = oi; }
            }
            if ((L & 3) == 0) {
                int row = mrow + mi * 16 + (L >> 2) + hf * 8;
                rv[wp * 128 + row] = v;
                ri[wp * 128 + row] = i;
            }
        }
    __syncthreads();
    if (tid < 128) {
        float v = rv[tid]; int i = ri[tid];
        {
            float ov = rv[128 + tid]; int oi = ri[128 + tid];
            if (ov > v) { v = ov; i = oi; }   // wp=1 has larger p; strict >
        }
        g_pv[pc * BATN + nbase + tid] = v;
        g_pi[pc * BATN + nbase + tid] = i;
    }
}

// ---------------- combine chunks + outputs + bincount ----------------
__global__ void combine_kernel(float* __restrict__ out) {
    int n = blockIdx.x * blockDim.x + threadIdx.x;
    if (n >= BATN) return;
    float v = g_pv[n]; int i = g_pi[n];
#pragma unroll
    for (int c = 1; c < PCHUNKS; c++) {
        float cv = g_pv[c * BATN + n]; int ci = g_pi[c * BATN + n];
        if (cv > v) { v = cv; i = ci; }       // chunks ascending in p
    }
    out[n]        = v;
    out[BATN + n] = (float)i;
    atomicAdd(&out[2 * BATN + i], 1.0f / (float)BATN);
}

// ---------------- launch ----------------
extern "C" void kernel_launch(void* const* d_in, const int* in_sizes, int n_in,
                              void* d_out, int out_size) {
    const float* P = (const float*)d_in[0];   // h_P [16384,100]
    const float* h = (const float*)d_in[1];   // h   [16384]
    const float* X = (const float*)d_in[2];   // volP[8192,100]
    float* out = (float*)d_out;
    (void)in_sizes; (void)n_in; (void)out_size;

    static bool attr_set = false;
    if (!attr_set) {
        cudaFuncSetAttribute(ot_mma_kernel,
                             cudaFuncAttributeMaxDynamicSharedMemorySize, SMEM_TOTAL);
        attr_set = true;
    }

    __half* a; cudaGetSymbolAddress((void**)&a, g_A);
    __half* b; cudaGetSymbolAddress((void**)&b, g_B);

    zero_g_kernel<<<(NUM_P + 255) / 256, 256>>>(out + 2 * BATN);
    expand_kernel<<<((int)(BATN  * KEXP) + 255) / 256, 256>>>(X, a, BATN,  0);
    expand_kernel<<<((int)(NUM_P * KEXP) + 255) / 256, 256>>>(P, b, NUM_P, 1);
    ot_mma_kernel<<<64 * PCHUNKS, THREADS, SMEM_TOTAL>>>(h);
    combine_kernel<<<(BATN + 255) / 256, 256>>>(out);
}

// round 9
// speedup vs baseline: 4.4358x; 1.0936x over previous
#include <cuda_runtime.h>
#include <cuda_fp16.h>
#include <math_constants.h>
#include <cstdint>

// ============================================================================
// scores = h_P @ volP^T + h ; per-column (over p) max/argmax ; bincount/8192.
// 2-way fp16 split, 3 cross products in ONE fp16 GEMM via K-concatenation:
//   A' (volP): [ah(100) | ah(100) | al(100) | 0(20)]   K = 320
//   B' (h_P) : [bh(100) | bl(100) | bh(100) | 0(20)]
// A-STATIONARY: block holds its 64-row A tile (41KB, 656B row pad) resident in
// smem for all p-tiles; only B streams through a 3-stage cp.async pipeline.
// 128-thr CTAs, warp tile 64n x 32p, 3 CTAs/SM.
// ============================================================================

#define NUM_P   16384
#define BATN    8192
#define DIM     100
#define KEXP    320
#define KSTEPS  10                  // 32-K steps per p-tile
#define PCHUNKS 16
#define PCH     (NUM_P / PCHUNKS)   // 1024
#define NT      64                  // n rows per block
#define TP      128                 // p rows per tile
#define PTILES  (PCH / TP)          // 8
#define TOT     (PTILES * KSTEPS)   // 80
#define THREADS 128

// smem layout (bytes):
//   A resident: 64 rows x 656B  = 41984
//   B stages  : 3 x (128 x 80B) = 30720   at ABOFF
//   reduce    : 2048            at REDOFF
#define AROW_B      656
#define BROW_B      80
#define ABOFF       41984
#define BSTAGE_B    10240
#define REDOFF      (ABOFF + 3 * BSTAGE_B)   // 72704
#define SMEM_TOTAL  (REDOFF + 2048)          // 74752

// ---------------- device scratch ----------------
__device__ __half g_A[(size_t)BATN  * KEXP];   // 5.2 MB
__device__ __half g_B[(size_t)NUM_P * KEXP];   // 10.5 MB
__device__ float g_pv[PCHUNKS * BATN];
__device__ int   g_pi[PCHUNKS * BATN];

// ---------------- asm helpers ----------------
__device__ __forceinline__ uint32_t smem_u32(const void* p) {
    uint32_t a;
    asm("{ .reg .u64 t; cvta.to.shared.u64 t, %1; cvt.u32.u64 %0, t; }" : "=r"(a) : "l"(p));
    return a;
}
__device__ __forceinline__ void cp16(uint32_t saddr, const void* gptr) {
    asm volatile("cp.async.cg.shared.global [%0], [%1], 16;"
                 :: "r"(saddr), "l"(__cvta_generic_to_global((void*)gptr)) : "memory");
}
#define CP_COMMIT() asm volatile("cp.async.commit_group;" ::: "memory")
#define CP_WAIT(n)  asm volatile("cp.async.wait_group %0;" :: "n"(n) : "memory")

#define LDSM4(r, addr) \
    asm volatile("ldmatrix.sync.aligned.m8n8.x4.shared.b16 {%0,%1,%2,%3}, [%4];" \
        : "=r"((r)[0]), "=r"((r)[1]), "=r"((r)[2]), "=r"((r)[3]) : "r"(addr))

#define MMA16816(c, a, b0, b1) \
    asm volatile("mma.sync.aligned.m16n8k16.row.col.f32.f16.f16.f32 " \
        "{%0,%1,%2,%3},{%4,%5,%6,%7},{%8,%9},{%0,%1,%2,%3};" \
        : "+f"((c)[0]), "+f"((c)[1]), "+f"((c)[2]), "+f"((c)[3]) \
        : "r"((a)[0]), "r"((a)[1]), "r"((a)[2]), "r"((a)[3]), "r"(b0), "r"(b1))

// ---------------- kernel: zero g ----------------
__global__ void zero_g_kernel(float* __restrict__ g) {
    int i = blockIdx.x * blockDim.x + threadIdx.x;
    if (i < NUM_P) g[i] = 0.0f;
}

// ---------------- kernel: fp16 split + K-concat expand ----------------
__global__ void expand_kernel(const float* __restrict__ src,
                              __half* __restrict__ dst,
                              int rows, int isB) {
    int idx = blockIdx.x * blockDim.x + threadIdx.x;
    if (idx >= rows * KEXP) return;
    int row = idx / KEXP, k = idx - row * KEXP;
    int blk = (k < 100) ? 0 : (k < 200) ? 1 : (k < 300) ? 2 : 3;
    int kk = k - blk * 100;
    __half o = __float2half_rn(0.0f);
    if (blk < 3) {
        float x = src[row * DIM + kk];
        __half hi = __float2half_rn(x);
        if (isB) {      // [bh bl bh]
            if (blk == 1) o = __float2half_rn(x - __half2float(hi));
            else          o = hi;
        } else {        // [ah ah al]
            if (blk == 2) o = __float2half_rn(x - __half2float(hi));
            else          o = hi;
        }
    }
    dst[idx] = o;
}

// ---------------- main fused GEMM + argmax ----------------
__global__ __launch_bounds__(THREADS, 3)
void ot_mma_kernel(const float* __restrict__ h) {
    extern __shared__ char smem[];
    const uint32_t smb = smem_u32(smem);
    const int tid = threadIdx.x;
    const int L   = tid & 31;
    const int wp  = tid >> 5;          // 0..3 : p-dim slice (32 cols each)
    const int nt  = blockIdx.x >> 4;   // 0..127
    const int pc  = blockIdx.x & 15;   // 0..15
    const int nbase  = nt * NT;
    const int pchunk = pc * PCH;

    // ldmatrix lane geometry
    const int mat = L >> 3, l8 = L & 7;
    const int arow = ((mat & 1) << 3) + l8, akh = (mat >> 1) << 3;
    const int brow = ((mat >> 1) << 3) + l8, bkh = (mat & 1) << 3;
    uint32_t aoffb[4], boffb[2];
#pragma unroll
    for (int mi = 0; mi < 4; mi++)       // A resident: row stride 656B
        aoffb[mi] = (uint32_t)((mi * 16 + arow) * AROW_B + akh * 2);
#pragma unroll
    for (int g = 0; g < 2; g++)          // B stage-relative: row stride 80B
        boffb[g] = (uint32_t)((wp * 32 + g * 16 + brow) * BROW_B + bkh * 2);

    // ---- prologue: A resident load (2560 x 16B) + B stages 0,1
    {
        const __half* Ab = g_A + (size_t)nbase * KEXP;
#pragma unroll
        for (int i = 0; i < 20; i++) {
            int q = tid + i * THREADS;          // 0..2559
            int row = q / 40, c = q - row * 40;
            cp16(smb + (uint32_t)(row * AROW_B + c * 16),
                 Ab + (size_t)row * KEXP + c * 8);
        }
    }
    const int cr = tid >> 2, cc = tid & 3;      // B load map: 4 chunks/thread
    const __half* bB = g_B + (size_t)(pchunk + cr) * KEXP + cc * 8;

#define LOAD_BSTAGE(stageaddr, srcB_, ksB) do {                                  \
    const uint32_t _st = (stageaddr);                                            \
    _Pragma("unroll")                                                            \
    for (int _i = 0; _i < 4; _i++)                                               \
        cp16(_st + (uint32_t)((cr + _i * 32) * BROW_B + cc * 16),                \
             (srcB_) + (size_t)_i * 32 * KEXP + (ksB) * 32);                     \
} while (0)

    LOAD_BSTAGE(smb + ABOFF, bB, 0);
    CP_COMMIT();                                // group: A + B stage0
    LOAD_BSTAGE(smb + ABOFF + BSTAGE_B, bB, 1);
    CP_COMMIT();                                // group: B stage1

    float acc[4][4][4];
#pragma unroll
    for (int mi = 0; mi < 4; mi++)
#pragma unroll
        for (int ni = 0; ni < 4; ni++)
#pragma unroll
            for (int q = 0; q < 4; q++) acc[mi][ni][q] = 0.0f;

    float bv[4][2];
    int   bi[4][2];
#pragma unroll
    for (int mi = 0; mi < 4; mi++)
#pragma unroll
        for (int hf = 0; hf < 2; hf++) { bv[mi][hf] = -CUDART_INF_F; bi[mi][hf] = 0; }

    int ks = 0, p0 = pchunk;           // current tile state
    int pfk = 2;                       // prefetch k-step within its tile
    const __half* pB = bB;             // prefetch-tile B base

    for (int gs = 0; gs < TOT; gs++) {
        CP_WAIT(1);
        __syncthreads();

        // prefetch B stage for step gs+2 (rolls across tile boundaries)
        if (gs + 2 < TOT) {
            LOAD_BSTAGE(smb + ABOFF + (uint32_t)((gs + 2) % 3) * BSTAGE_B, pB, pfk);
        }
        CP_COMMIT();
        if (++pfk == KSTEPS) { pfk = 0; pB += (size_t)TP * KEXP; }

        // compute: A from resident smem (K offset = ks*64 bytes), B from stage
        const uint32_t sbB = smb + ABOFF + (uint32_t)(gs % 3) * BSTAGE_B;
        const uint32_t ak  = (uint32_t)(ks * 64);
#pragma unroll
        for (int kh = 0; kh < 2; kh++) {
            const uint32_t ko = (uint32_t)kh * 32;
            uint32_t af[4][4], bf[2][4];
#pragma unroll
            for (int mi = 0; mi < 4; mi++) LDSM4(af[mi], smb + aoffb[mi] + ak + ko);
#pragma unroll
            for (int g = 0; g < 2; g++)    LDSM4(bf[g], sbB + boffb[g] + ko);
#pragma unroll
            for (int mi = 0; mi < 4; mi++)
#pragma unroll
                for (int ni = 0; ni < 4; ni++) {
                    const int g = ni >> 1, q = (ni & 1) * 2;
                    MMA16816(acc[mi][ni], af[mi], bf[g][q], bf[g][q + 1]);
                }
        }

        // end of p-tile: fold accumulators (register-only; no barrier needed)
        if (ks == KSTEPS - 1) {
#pragma unroll
            for (int ni = 0; ni < 4; ni++) {
                const int pA = p0 + wp * 32 + ni * 8 + (L & 3) * 2;
                const float h0 = __ldg(h + pA), h1 = __ldg(h + pA + 1);
#pragma unroll
                for (int mi = 0; mi < 4; mi++)
#pragma unroll
                    for (int hf = 0; hf < 2; hf++) {
                        float s0 = acc[mi][ni][hf * 2 + 0] + h0;
                        float s1 = acc[mi][ni][hf * 2 + 1] + h1;
                        if (s0 > bv[mi][hf]) { bv[mi][hf] = s0; bi[mi][hf] = pA; }
                        if (s1 > bv[mi][hf]) { bv[mi][hf] = s1; bi[mi][hf] = pA + 1; }
                        acc[mi][ni][hf * 2 + 0] = 0.0f;
                        acc[mi][ni][hf * 2 + 1] = 0.0f;
                    }
            }
            ks = 0; p0 += TP;
        } else {
            ks++;
        }
    }

    // reduce: lanes sharing an n-row differ in L&3 (disjoint p); then across
    // the 4 warps (disjoint p slices, wp ascending = p ascending).
    __syncthreads();
    float* rv = reinterpret_cast<float*>(smem + REDOFF);          // [4][64]
    int*   ri = reinterpret_cast<int*>(smem + REDOFF + 1024);     // [4][64]
#pragma unroll
    for (int mi = 0; mi < 4; mi++)
#pragma unroll
        for (int hf = 0; hf < 2; hf++) {
            float v = bv[mi][hf];
            int   i = bi[mi][hf];
#pragma unroll
            for (int off = 1; off <= 2; off <<= 1) {
                float ov = __shfl_xor_sync(0xffffffffu, v, off);
                int   oi = __shfl_xor_sync(0xffffffffu, i, off);
                if (ov > v || (ov == v && oi < i)) { v = ov; i = oi; }
            }
            if ((L & 3) == 0) {
                int row = mi * 16 + (L >> 2) + hf * 8;            // 0..63
                rv[wp * 64 + row] = v;
                ri[wp * 64 + row] = i;
            }
        }
    __syncthreads();
    if (tid < NT) {
        float v = rv[tid]; int i = ri[tid];
#pragma unroll
        for (int w = 1; w < 4; w++) {
            float ov = rv[w * 64 + tid]; int oi = ri[w * 64 + tid];
            if (ov > v) { v = ov; i = oi; }
        }
        g_pv[pc * BATN + nbase + tid] = v;
        g_pi[pc * BATN + nbase + tid] = i;
    }
}

// ---------------- combine chunks + outputs + bincount ----------------
__global__ void combine_kernel(float* __restrict__ out) {
    int n = blockIdx.x * blockDim.x + threadIdx.x;
    if (n >= BATN) return;
    float v = g_pv[n]; int i = g_pi[n];
#pragma unroll
    for (int c = 1; c < PCHUNKS; c++) {
        float cv = g_pv[c * BATN + n]; int ci = g_pi[c * BATN + n];
        if (cv > v) { v = cv; i = ci; }       // chunks ascending in p
    }
    out[n]        = v;
    out[BATN + n] = (float)i;
    atomicAdd(&out[2 * BATN + i], 1.0f / (float)BATN);
}

// ---------------- launch ----------------
extern "C" void kernel_launch(void* const* d_in, const int* in_sizes, int n_in,
                              void* d_out, int out_size) {
    const float* P = (const float*)d_in[0];   // h_P [16384,100]
    const float* h = (const float*)d_in[1];   // h   [16384]
    const float* X = (const float*)d_in[2];   // volP[8192,100]
    float* out = (float*)d_out;
    (void)in_sizes; (void)n_in; (void)out_size;

    static bool attr_set = false;
    if (!attr_set) {
        cudaFuncSetAttribute(ot_mma_kernel,
                             cudaFuncAttributeMaxDynamicSharedMemorySize, SMEM_TOTAL);
        attr_set = true;
    }

    __half* a; cudaGetSymbolAddress((void**)&a, g_A);
    __half* b; cudaGetSymbolAddress((void**)&b, g_B);

    zero_g_kernel<<<(NUM_P + 255) / 256, 256>>>(out + 2 * BATN);
    expand_kernel<<<((int)(BATN  * KEXP) + 255) / 256, 256>>>(X, a, BATN,  0);
    expand_kernel<<<((int)(NUM_P * KEXP) + 255) / 256, 256>>>(P, b, NUM_P, 1);
    ot_mma_kernel<<<128 * PCHUNKS, THREADS, SMEM_TOTAL>>>(h);
    combine_kernel<<<(BATN + 255) / 256, 256>>>(out);
}

// round 11
// speedup vs baseline: 5.4618x; 1.2313x over previous
#include <cuda_runtime.h>
#include <cuda_fp16.h>
#include <math_constants.h>
#include <cstdint>

// ============================================================================
// scores = h_P @ volP^T + h ; per-column (over p) max/argmax ; bincount/8192.
// 2-way fp16 split, 3 cross products in ONE fp16 GEMM via K-concatenation:
//   A' (volP): [ah(100) | ah(100) | al(100) | 0(20)]   K = 320
//   B' (h_P) : [bh(100) | bl(100) | bh(100) | 0(20)]
// A-STATIONARY + WARP-DECOUPLED: A tile resident in smem (written once);
// each warp streams ITS OWN 32-row B slice through a private 3-stage cp.async
// pipeline. No __syncthreads in the main loop — only __syncwarp.
// 128-thr CTAs, warp tile 64n x 32p, 3 CTAs/SM.
// R11 fix: dBw is stage-relative (R10 double-added ABOFF -> smem OOB).
// ============================================================================

#define NUM_P   16384
#define BATN    8192
#define DIM     100
#define KEXP    320
#define KSTEPS  10                  // 32-K steps per p-tile
#define PCHUNKS 16
#define PCH     (NUM_P / PCHUNKS)   // 1024
#define NT      64                  // n rows per block
#define TP      128                 // p rows per tile
#define PTILES  (PCH / TP)          // 8
#define TOT     (PTILES * KSTEPS)   // 80
#define THREADS 128

// smem layout (bytes):
//   A resident: 64 rows x 656B  = 41984
//   B stages  : 3 x (128 x 80B) = 30720   at ABOFF
//   reduce    : 2048            at REDOFF
#define AROW_B      656
#define BROW_B      80
#define ABOFF       41984
#define BSTAGE_B    10240
#define REDOFF      (ABOFF + 3 * BSTAGE_B)   // 72704
#define SMEM_TOTAL  (REDOFF + 2048)          // 74752

// ---------------- device scratch ----------------
__device__ __half g_A[(size_t)BATN  * KEXP];   // 5.2 MB
__device__ __half g_B[(size_t)NUM_P * KEXP];   // 10.5 MB
__device__ float g_pv[PCHUNKS * BATN];
__device__ int   g_pi[PCHUNKS * BATN];

// ---------------- asm helpers ----------------
__device__ __forceinline__ uint32_t smem_u32(const void* p) {
    uint32_t a;
    asm("{ .reg .u64 t; cvta.to.shared.u64 t, %1; cvt.u32.u64 %0, t; }" : "=r"(a) : "l"(p));
    return a;
}
__device__ __forceinline__ void cp16(uint32_t saddr, const void* gptr) {
    asm volatile("cp.async.cg.shared.global [%0], [%1], 16;"
                 :: "r"(saddr), "l"(__cvta_generic_to_global((void*)gptr)) : "memory");
}
#define CP_COMMIT() asm volatile("cp.async.commit_group;" ::: "memory")
#define CP_WAIT(n)  asm volatile("cp.async.wait_group %0;" :: "n"(n) : "memory")

#define LDSM4(r, addr) \
    asm volatile("ldmatrix.sync.aligned.m8n8.x4.shared.b16 {%0,%1,%2,%3}, [%4];" \
        : "=r"((r)[0]), "=r"((r)[1]), "=r"((r)[2]), "=r"((r)[3]) : "r"(addr))

#define MMA16816(c, a, b0, b1) \
    asm volatile("mma.sync.aligned.m16n8k16.row.col.f32.f16.f16.f32 " \
        "{%0,%1,%2,%3},{%4,%5,%6,%7},{%8,%9},{%0,%1,%2,%3};" \
        : "+f"((c)[0]), "+f"((c)[1]), "+f"((c)[2]), "+f"((c)[3]) \
        : "r"((a)[0]), "r"((a)[1]), "r"((a)[2]), "r"((a)[3]), "r"(b0), "r"(b1))

// ---------------- kernel: zero g ----------------
__global__ void zero_g_kernel(float* __restrict__ g) {
    int i = blockIdx.x * blockDim.x + threadIdx.x;
    if (i < NUM_P) g[i] = 0.0f;
}

// ---------------- kernel: fp16 split + K-concat expand (block = one row) ----
__global__ void expand_kernel(const float* __restrict__ src,
                              __half* __restrict__ dst, int isB) {
    const int row = blockIdx.x;
    const int k = threadIdx.x * 2;            // 0,2,..,318 ; pairs never straddle
    __half2 o = __floats2half2_rn(0.0f, 0.0f);
    const int blk = (k < 100) ? 0 : (k < 200) ? 1 : (k < 300) ? 2 : 3;
    if (blk < 3) {
        const int kk = k - blk * 100;
        float2 v = *reinterpret_cast<const float2*>(src + (size_t)row * DIM + kk);
        __half h0 = __float2half_rn(v.x), h1 = __float2half_rn(v.y);
        bool want_lo = isB ? (blk == 1) : (blk == 2);
        if (want_lo) {
            o = __halves2half2(__float2half_rn(v.x - __half2float(h0)),
                               __float2half_rn(v.y - __half2float(h1)));
        } else {
            o = __halves2half2(h0, h1);
        }
    }
    *reinterpret_cast<__half2*>(dst + (size_t)row * KEXP + k) = o;
}

// ---------------- main fused GEMM + argmax ----------------
__global__ __launch_bounds__(THREADS, 3)
void ot_mma_kernel(const float* __restrict__ h) {
    extern __shared__ char smem[];
    const uint32_t smb = smem_u32(smem);
    const int tid = threadIdx.x;
    const int L   = tid & 31;
    const int wp  = tid >> 5;          // 0..3 : p-dim slice (32 cols each)
    const int nt  = blockIdx.x >> 4;   // 0..127
    const int pc  = blockIdx.x & 15;   // 0..15
    const int nbase  = nt * NT;
    const int pchunk = pc * PCH;

    // ldmatrix lane geometry
    const int mat = L >> 3, l8 = L & 7;
    const int arow = ((mat & 1) << 3) + l8, akh = (mat >> 1) << 3;
    const int brow = ((mat >> 1) << 3) + l8, bkh = (mat & 1) << 3;
    uint32_t aoffb[4], boffb[2];
#pragma unroll
    for (int mi = 0; mi < 4; mi++)       // A resident: row stride 656B
        aoffb[mi] = (uint32_t)((mi * 16 + arow) * AROW_B + akh * 2);
#pragma unroll
    for (int g = 0; g < 2; g++)          // B stage-relative: row stride 80B
        boffb[g] = (uint32_t)((wp * 32 + g * 16 + brow) * BROW_B + bkh * 2);

    // per-warp B loader: warp wp owns B rows [wp*32, wp*32+32) of each tile.
    // lane L -> rows wp*32 + (L>>2) + 8i (i=0..3), 16B chunk (L&3).
    // dBw is STAGE-RELATIVE (the stage address passed in carries ABOFF).
    const int brow0 = wp * 32 + (L >> 2);
    const uint32_t dBw = (uint32_t)(brow0 * BROW_B + (L & 3) * 16);
    const __half* bBw = g_B + (size_t)(pchunk + brow0) * KEXP + (L & 3) * 8;

#define LOAD_BSTAGE(stageaddr, srcB_, ksB) do {                                  \
    const uint32_t _st = (stageaddr);                                            \
    _Pragma("unroll")                                                            \
    for (int _i = 0; _i < 4; _i++)                                               \
        cp16(_st + dBw + (uint32_t)_i * 8 * BROW_B,                              \
             (srcB_) + (size_t)_i * 8 * KEXP + (ksB) * 32);                      \
} while (0)

    // ---- prologue
    // G0: A resident (2560 x 16B, all threads)
    {
        const __half* Ab = g_A + (size_t)nbase * KEXP;
#pragma unroll
        for (int i = 0; i < 20; i++) {
            int q = tid + i * THREADS;          // 0..2559
            int row = q / 40, c = q - row * 40;
            cp16(smb + (uint32_t)(row * AROW_B + c * 16),
                 Ab + (size_t)row * KEXP + c * 8);
        }
        CP_COMMIT();
    }
    // G1: B stage 0 ; G2: B stage 1  (per-warp slices)
    LOAD_BSTAGE(smb + ABOFF, bBw, 0);
    CP_COMMIT();
    LOAD_BSTAGE(smb + ABOFF + BSTAGE_B, bBw, 1);
    CP_COMMIT();
    CP_WAIT(2);            // G0 (this thread's A chunks) landed
    __syncthreads();       // ALL threads' A chunks landed -> A readable by all

    float acc[4][4][4];
#pragma unroll
    for (int mi = 0; mi < 4; mi++)
#pragma unroll
        for (int ni = 0; ni < 4; ni++)
#pragma unroll
            for (int q = 0; q < 4; q++) acc[mi][ni][q] = 0.0f;

    float bv[4][2];
    int   bi[4][2];
#pragma unroll
    for (int mi = 0; mi < 4; mi++)
#pragma unroll
        for (int hf = 0; hf < 2; hf++) { bv[mi][hf] = -CUDART_INF_F; bi[mi][hf] = 0; }

    int ks = 0, p0 = pchunk;           // current tile state
    int pfk = 2;                       // prefetch k-step within its tile
    const __half* pBw = bBw;           // prefetch-tile B base (per warp)

    for (int gs = 0; gs < TOT; gs++) {
        CP_WAIT(1);        // this warp's stage gs landed (1 group/step/thread)
        __syncwarp();      // publish lanes' cp.async bytes across the warp

        // prefetch this warp's B slice for step gs+2 (rolls across tiles)
        if (gs + 2 < TOT) {
            LOAD_BSTAGE(smb + ABOFF + (uint32_t)((gs + 2) % 3) * BSTAGE_B, pBw, pfk);
        }
        CP_COMMIT();       // exactly one group per step keeps wait-count math
        if (++pfk == KSTEPS) { pfk = 0; pBw += (size_t)TP * KEXP; }

        // compute: A resident (K offset ks*64B), B from this warp's stage slice
        const uint32_t sbB = smb + ABOFF + (uint32_t)(gs % 3) * BSTAGE_B;
        const uint32_t ak  = (uint32_t)(ks * 64);
#pragma unroll
        for (int kh = 0; kh < 2; kh++) {
            const uint32_t ko = (uint32_t)kh * 32;
            uint32_t af[4][4], bf[2][4];
#pragma unroll
            for (int mi = 0; mi < 4; mi++) LDSM4(af[mi], smb + aoffb[mi] + ak + ko);
#pragma unroll
            for (int g = 0; g < 2; g++)    LDSM4(bf[g], sbB + boffb[g] + ko);
#pragma unroll
            for (int mi = 0; mi < 4; mi++)
#pragma unroll
                for (int ni = 0; ni < 4; ni++) {
                    const int g = ni >> 1, q = (ni & 1) * 2;
                    MMA16816(acc[mi][ni], af[mi], bf[g][q], bf[g][q + 1]);
                }
        }

        // end of p-tile: fold accumulators (register-only)
        if (ks == KSTEPS - 1) {
#pragma unroll
            for (int ni = 0; ni < 4; ni++) {
                const int pA = p0 + wp * 32 + ni * 8 + (L & 3) * 2;
                const float h0 = __ldg(h + pA), h1 = __ldg(h + pA + 1);
#pragma unroll
                for (int mi = 0; mi < 4; mi++)
#pragma unroll
                    for (int hf = 0; hf < 2; hf++) {
                        float s0 = acc[mi][ni][hf * 2 + 0] + h0;
                        float s1 = acc[mi][ni][hf * 2 + 1] + h1;
                        if (s0 > bv[mi][hf]) { bv[mi][hf] = s0; bi[mi][hf] = pA; }
                        if (s1 > bv[mi][hf]) { bv[mi][hf] = s1; bi[mi][hf] = pA + 1; }
                        acc[mi][ni][hf * 2 + 0] = 0.0f;
                        acc[mi][ni][hf * 2 + 1] = 0.0f;
                    }
            }
            ks = 0; p0 += TP;
        } else {
            ks++;
        }
    }

    // reduce: lanes sharing an n-row differ in L&3 (disjoint p); then across
    // the 4 warps (disjoint p slices, wp ascending = p ascending).
    __syncthreads();
    float* rv = reinterpret_cast<float*>(smem + REDOFF);          // [4][64]
    int*   ri = reinterpret_cast<int*>(smem + REDOFF + 1024);     // [4][64]
#pragma unroll
    for (int mi = 0; mi < 4; mi++)
#pragma unroll
        for (int hf = 0; hf < 2; hf++) {
            float v = bv[mi][hf];
            int   i = bi[mi][hf];
#pragma unroll
            for (int off = 1; off <= 2; off <<= 1) {
                float ov = __shfl_xor_sync(0xffffffffu, v, off);
                int   oi = __shfl_xor_sync(0xffffffffu, i, off);
                if (ov > v || (ov == v && oi < i)) { v = ov; i = oi; }
            }
            if ((L & 3) == 0) {
                int row = mi * 16 + (L >> 2) + hf * 8;            // 0..63
                rv[wp * 64 + row] = v;
                ri[wp * 64 + row] = i;
            }
        }
    __syncthreads();
    if (tid < NT) {
        float v = rv[tid]; int i = ri[tid];
#pragma unroll
        for (int w = 1; w < 4; w++) {
            float ov = rv[w * 64 + tid]; int oi = ri[w * 64 + tid];
            if (ov > v) { v = ov; i = oi; }
        }
        g_pv[pc * BATN + nbase + tid] = v;
        g_pi[pc * BATN + nbase + tid] = i;
    }
}

// ---------------- combine chunks + outputs + bincount ----------------
__global__ void combine_kernel(float* __restrict__ out) {
    int n = blockIdx.x * blockDim.x + threadIdx.x;
    if (n >= BATN) return;
    float v = g_pv[n]; int i = g_pi[n];
#pragma unroll
    for (int c = 1; c < PCHUNKS; c++) {
        float cv = g_pv[c * BATN + n]; int ci = g_pi[c * BATN + n];
        if (cv > v) { v = cv; i = ci; }       // chunks ascending in p
    }
    out[n]        = v;
    out[BATN + n] = (float)i;
    atomicAdd(&out[2 * BATN + i], 1.0f / (float)BATN);
}

// ---------------- launch ----------------
extern "C" void kernel_launch(void* const* d_in, const int* in_sizes, int n_in,
                              void* d_out, int out_size) {
    const float* P = (const float*)d_in[0];   // h_P [16384,100]
    const float* h = (const float*)d_in[1];   // h   [16384]
    const float* X = (const float*)d_in[2];   // volP[8192,100]
    float* out = (float*)d_out;
    (void)in_sizes; (void)n_in; (void)out_size;

    static bool attr_set = false;
    if (!attr_set) {
        cudaFuncSetAttribute(ot_mma_kernel,
                             cudaFuncAttributeMaxDynamicSharedMemorySize, SMEM_TOTAL);
        attr_set = true;
    }

    __half* a; cudaGetSymbolAddress((void**)&a, g_A);
    __half* b; cudaGetSymbolAddress((void**)&b, g_B);

    zero_g_kernel<<<(NUM_P + 255) / 256, 256>>>(out + 2 * BATN);
    expand_kernel<<<BATN,  KEXP / 2>>>(X, a, 0);
    expand_kernel<<<NUM_P, KEXP / 2>>>(P, b, 1);
    ot_mma_kernel<<<128 * PCHUNKS, THREADS, SMEM_TOTAL>>>(h);
    combine_kernel<<<(BATN + 255) / 256, 256>>>(out);
}

// round 12
// speedup vs baseline: 5.6432x; 1.0332x over previous
#include <cuda_runtime.h>
#include <cuda_fp16.h>
#include <math_constants.h>
#include <cstdint>

// ============================================================================
// scores = h_P @ volP^T + h ; per-column (over p) max/argmax ; bincount/8192.
// 2-way fp16 split, 3 cross products in ONE fp16 GEMM via K-concatenation:
//   A' (volP): [ah(100) | ah(100) | al(100) | 0(20)]   K = 320
//   B' (h_P) : [bh(100) | bl(100) | bh(100) | 0(20)]
// A-STATIONARY + WARP-DECOUPLED, fat warp tile 64n x 64p (acc 128 regs):
// A tile resident in smem; each warp streams ITS OWN 64-row B slice through a
// private 3-stage cp.async pipeline. No __syncthreads in main loop.
// 128-thr CTAs (4 warps), block tile 64n x 256p, 2 CTAs/SM.
// ============================================================================

#define NUM_P   16384
#define BATN    8192
#define DIM     100
#define KEXP    320
#define KSTEPS  10                  // 32-K steps per p-tile
#define PCHUNKS 16
#define PCH     (NUM_P / PCHUNKS)   // 1024
#define NT      64                  // n rows per block
#define TP      256                 // p rows per tile (64 per warp)
#define PTILES  (PCH / TP)          // 4
#define TOT     (PTILES * KSTEPS)   // 40
#define THREADS 128

// smem layout (bytes):
//   A resident: 64 rows x 656B   = 41984
//   B stages  : 3 x (256 x 80B)  = 61440   at ABOFF
//   reduce    : 2048             at REDOFF
#define AROW_B      656
#define BROW_B      80
#define ABOFF       41984
#define BSTAGE_B    20480
#define REDOFF      (ABOFF + 3 * BSTAGE_B)   // 103424
#define SMEM_TOTAL  (REDOFF + 2048)          // 105472

// ---------------- device scratch ----------------
__device__ __half g_A[(size_t)BATN  * KEXP];   // 5.2 MB
__device__ __half g_B[(size_t)NUM_P * KEXP];   // 10.5 MB
__device__ float g_pv[PCHUNKS * BATN];
__device__ int   g_pi[PCHUNKS * BATN];

// ---------------- asm helpers ----------------
__device__ __forceinline__ uint32_t smem_u32(const void* p) {
    uint32_t a;
    asm("{ .reg .u64 t; cvta.to.shared.u64 t, %1; cvt.u32.u64 %0, t; }" : "=r"(a) : "l"(p));
    return a;
}
__device__ __forceinline__ void cp16(uint32_t saddr, const void* gptr) {
    asm volatile("cp.async.cg.shared.global [%0], [%1], 16;"
                 :: "r"(saddr), "l"(__cvta_generic_to_global((void*)gptr)) : "memory");
}
#define CP_COMMIT() asm volatile("cp.async.commit_group;" ::: "memory")
#define CP_WAIT(n)  asm volatile("cp.async.wait_group %0;" :: "n"(n) : "memory")

#define LDSM4(r, addr) \
    asm volatile("ldmatrix.sync.aligned.m8n8.x4.shared.b16 {%0,%1,%2,%3}, [%4];" \
        : "=r"((r)[0]), "=r"((r)[1]), "=r"((r)[2]), "=r"((r)[3]) : "r"(addr))

#define MMA16816(c, a, b0, b1) \
    asm volatile("mma.sync.aligned.m16n8k16.row.col.f32.f16.f16.f32 " \
        "{%0,%1,%2,%3},{%4,%5,%6,%7},{%8,%9},{%0,%1,%2,%3};" \
        : "+f"((c)[0]), "+f"((c)[1]), "+f"((c)[2]), "+f"((c)[3]) \
        : "r"((a)[0]), "r"((a)[1]), "r"((a)[2]), "r"((a)[3]), "r"(b0), "r"(b1))

// ---------------- kernel: zero g ----------------
__global__ void zero_g_kernel(float* __restrict__ g) {
    int i = blockIdx.x * blockDim.x + threadIdx.x;
    if (i < NUM_P) g[i] = 0.0f;
}

// ---------------- kernel: fp16 split + K-concat expand (block = one row) ----
__global__ void expand_kernel(const float* __restrict__ src,
                              __half* __restrict__ dst, int isB) {
    const int row = blockIdx.x;
    const int k = threadIdx.x * 2;            // 0,2,..,318 ; pairs never straddle
    __half2 o = __floats2half2_rn(0.0f, 0.0f);
    const int blk = (k < 100) ? 0 : (k < 200) ? 1 : (k < 300) ? 2 : 3;
    if (blk < 3) {
        const int kk = k - blk * 100;
        float2 v = *reinterpret_cast<const float2*>(src + (size_t)row * DIM + kk);
        __half h0 = __float2half_rn(v.x), h1 = __float2half_rn(v.y);
        bool want_lo = isB ? (blk == 1) : (blk == 2);
        if (want_lo) {
            o = __halves2half2(__float2half_rn(v.x - __half2float(h0)),
                               __float2half_rn(v.y - __half2float(h1)));
        } else {
            o = __halves2half2(h0, h1);
        }
    }
    *reinterpret_cast<__half2*>(dst + (size_t)row * KEXP + k) = o;
}

// ---------------- main fused GEMM + argmax ----------------
__global__ __launch_bounds__(THREADS, 2)
void ot_mma_kernel(const float* __restrict__ h) {
    extern __shared__ char smem[];
    const uint32_t smb = smem_u32(smem);
    const int tid = threadIdx.x;
    const int L   = tid & 31;
    const int wp  = tid >> 5;          // 0..3 : p-dim slice (64 cols each)
    const int nt  = blockIdx.x >> 4;   // 0..127
    const int pc  = blockIdx.x & 15;   // 0..15
    const int nbase  = nt * NT;
    const int pchunk = pc * PCH;

    // ldmatrix lane geometry
    const int mat = L >> 3, l8 = L & 7;
    const int arow = ((mat & 1) << 3) + l8, akh = (mat >> 1) << 3;
    const int brow = ((mat >> 1) << 3) + l8, bkh = (mat & 1) << 3;
    uint32_t aoffb[4], boffb[4];
#pragma unroll
    for (int mi = 0; mi < 4; mi++)       // A resident: row stride 656B
        aoffb[mi] = (uint32_t)((mi * 16 + arow) * AROW_B + akh * 2);
#pragma unroll
    for (int g = 0; g < 4; g++)          // B stage-relative: row stride 80B
        boffb[g] = (uint32_t)((wp * 64 + g * 16 + brow) * BROW_B + bkh * 2);

    // per-warp B loader: warp wp owns B rows [wp*64, wp*64+64) of each tile.
    // lane L -> rows wp*64 + (L>>2) + 8i (i=0..7), 16B chunk (L&3).
    // dBw is STAGE-RELATIVE (the stage address passed in carries ABOFF).
    const int brow0 = wp * 64 + (L >> 2);
    const uint32_t dBw = (uint32_t)(brow0 * BROW_B + (L & 3) * 16);
    const __half* bBw = g_B + (size_t)(pchunk + brow0) * KEXP + (L & 3) * 8;

#define LOAD_BSTAGE(stageaddr, srcB_, ksB) do {                                  \
    const uint32_t _st = (stageaddr);                                            \
    _Pragma("unroll")                                                            \
    for (int _i = 0; _i < 8; _i++)                                               \
        cp16(_st + dBw + (uint32_t)_i * 8 * BROW_B,                              \
             (srcB_) + (size_t)_i * 8 * KEXP + (ksB) * 32);                      \
} while (0)

    // ---- prologue
    // G0: A resident (2560 x 16B, all threads)
    {
        const __half* Ab = g_A + (size_t)nbase * KEXP;
#pragma unroll
        for (int i = 0; i < 20; i++) {
            int q = tid + i * THREADS;          // 0..2559
            int row = q / 40, c = q - row * 40;
            cp16(smb + (uint32_t)(row * AROW_B + c * 16),
                 Ab + (size_t)row * KEXP + c * 8);
        }
        CP_COMMIT();
    }
    // G1: B stage 0 ; G2: B stage 1  (per-warp slices)
    LOAD_BSTAGE(smb + ABOFF, bBw, 0);
    CP_COMMIT();
    LOAD_BSTAGE(smb + ABOFF + BSTAGE_B, bBw, 1);
    CP_COMMIT();
    CP_WAIT(2);            // G0 (this thread's A chunks) landed
    __syncthreads();       // ALL threads' A chunks landed -> A readable by all

    float acc[4][8][4];
#pragma unroll
    for (int mi = 0; mi < 4; mi++)
#pragma unroll
        for (int pi = 0; pi < 8; pi++)
#pragma unroll
            for (int q = 0; q < 4; q++) acc[mi][pi][q] = 0.0f;

    float bv[4][2];
    int   bi[4][2];
#pragma unroll
    for (int mi = 0; mi < 4; mi++)
#pragma unroll
        for (int hf = 0; hf < 2; hf++) { bv[mi][hf] = -CUDART_INF_F; bi[mi][hf] = 0; }

    int ks = 0, p0 = pchunk;           // current tile state
    int pfk = 2;                       // prefetch k-step within its tile
    const __half* pBw = bBw;           // prefetch-tile B base (per warp)

    for (int gs = 0; gs < TOT; gs++) {
        CP_WAIT(1);        // this warp's stage gs landed (1 group/step/thread)
        __syncwarp();      // publish lanes' cp.async bytes across the warp

        // prefetch this warp's B slice for step gs+2 (rolls across tiles)
        if (gs + 2 < TOT) {
            LOAD_BSTAGE(smb + ABOFF + (uint32_t)((gs + 2) % 3) * BSTAGE_B, pBw, pfk);
        }
        CP_COMMIT();       // exactly one group per step keeps wait-count math
        if (++pfk == KSTEPS) { pfk = 0; pBw += (size_t)TP * KEXP; }

        // compute: A resident (K offset ks*64B), B from this warp's stage slice
        const uint32_t sbB = smb + ABOFF + (uint32_t)(gs % 3) * BSTAGE_B;
        const uint32_t ak  = (uint32_t)(ks * 64);
#pragma unroll
        for (int kh = 0; kh < 2; kh++) {
            const uint32_t ko = (uint32_t)kh * 32;
            uint32_t af[4][4], bf[4][4];
#pragma unroll
            for (int mi = 0; mi < 4; mi++) LDSM4(af[mi], smb + aoffb[mi] + ak + ko);
#pragma unroll
            for (int g = 0; g < 4; g++)    LDSM4(bf[g], sbB + boffb[g] + ko);
#pragma unroll
            for (int mi = 0; mi < 4; mi++)
#pragma unroll
                for (int pi = 0; pi < 8; pi++) {
                    const int g = pi >> 1, q = (pi & 1) * 2;
                    MMA16816(acc[mi][pi], af[mi], bf[g][q], bf[g][q + 1]);
                }
        }

        // end of p-tile: fold accumulators (register-only)
        if (ks == KSTEPS - 1) {
#pragma unroll
            for (int pi = 0; pi < 8; pi++) {
                const int pA = p0 + wp * 64 + pi * 8 + (L & 3) * 2;
                const float h0 = __ldg(h + pA), h1 = __ldg(h + pA + 1);
#pragma unroll
                for (int mi = 0; mi < 4; mi++)
#pragma unroll
                    for (int hf = 0; hf < 2; hf++) {
                        float s0 = acc[mi][pi][hf * 2 + 0] + h0;
                        float s1 = acc[mi][pi][hf * 2 + 1] + h1;
                        if (s0 > bv[mi][hf]) { bv[mi][hf] = s0; bi[mi][hf] = pA; }
                        if (s1 > bv[mi][hf]) { bv[mi][hf] = s1; bi[mi][hf] = pA + 1; }
                        acc[mi][pi][hf * 2 + 0] = 0.0f;
                        acc[mi][pi][hf * 2 + 1] = 0.0f;
                    }
            }
            ks = 0; p0 += TP;
        } else {
            ks++;
        }
    }

    // reduce: lanes sharing an n-row differ in L&3 (disjoint p); then across
    // the 4 warps (disjoint p slices, wp ascending = p ascending).
    __syncthreads();
    float* rv = reinterpret_cast<float*>(smem + REDOFF);          // [4][64]
    int*   ri = reinterpret_cast<int*>(smem + REDOFF + 1024);     // [4][64]
#pragma unroll
    for (int mi = 0; mi < 4; mi++)
#pragma unroll
        for (int hf = 0; hf < 2; hf++) {
            float v = bv[mi][hf];
            int   i = bi[mi][hf];
#pragma unroll
            for (int off = 1; off <= 2; off <<= 1) {
                float ov = __shfl_xor_sync(0xffffffffu, v, off);
                int   oi = __shfl_xor_sync(0xffffffffu, i, off);
                if (ov > v || (ov == v && oi < i)) { v = ov; i = oi; }
            }
            if ((L & 3) == 0) {
                int row = mi * 16 + (L >> 2) + hf * 8;            // 0..63
                rv[wp * 64 + row] = v;
                ri[wp * 64 + row] = i;
            }
        }
    __syncthreads();
    if (tid < NT) {
        float v = rv[tid]; int i = ri[tid];
#pragma unroll
        for (int w = 1; w < 4; w++) {
            float ov = rv[w * 64 + tid]; int oi = ri[w * 64 + tid];
            if (ov > v) { v = ov; i = oi; }
        }
        g_pv[pc * BATN + nbase + tid] = v;
        g_pi[pc * BATN + nbase + tid] = i;
    }
}

// ---------------- combine chunks + outputs + bincount ----------------
__global__ void combine_kernel(float* __restrict__ out) {
    int n = blockIdx.x * blockDim.x + threadIdx.x;
    if (n >= BATN) return;
    float v = g_pv[n]; int i = g_pi[n];
#pragma unroll
    for (int c = 1; c < PCHUNKS; c++) {
        float cv = g_pv[c * BATN + n]; int ci = g_pi[c * BATN + n];
        if (cv > v) { v = cv; i = ci; }       // chunks ascending in p
    }
    out[n]        = v;
    out[BATN + n] = (float)i;
    atomicAdd(&out[2 * BATN + i], 1.0f / (float)BATN);
}

// ---------------- launch ----------------
extern "C" void kernel_launch(void* const* d_in, const int* in_sizes, int n_in,
                              void* d_out, int out_size) {
    const float* P = (const float*)d_in[0];   // h_P [16384,100]
    const float* h = (const float*)d_in[1];   // h   [16384]
    const float* X = (const float*)d_in[2];   // volP[8192,100]
    float* out = (float*)d_out;
    (void)in_sizes; (void)n_in; (void)out_size;

    static bool attr_set = false;
    if (!attr_set) {
        cudaFuncSetAttribute(ot_mma_kernel,
                             cudaFuncAttributeMaxDynamicSharedMemorySize, SMEM_TOTAL);
        attr_set = true;
    }

    __half* a; cudaGetSymbolAddress((void**)&a, g_A);
    __half* b; cudaGetSymbolAddress((void**)&b, g_B);

    zero_g_kernel<<<(NUM_P + 255) / 256, 256>>>(out + 2 * BATN);
    expand_kernel<<<BATN,  KEXP / 2>>>(X, a, 0);
    expand_kernel<<<NUM_P, KEXP / 2>>>(P, b, 1);
    ot_mma_kernel<<<128 * PCHUNKS, THREADS, SMEM_TOTAL>>>(h);
    combine_kernel<<<(BATN + 255) / 256, 256>>>(out);
}